// round 10
// baseline (speedup 1.0000x reference)
#include <cuda_runtime.h>
#include <cuda_fp16.h>
#include <math.h>
#include <stdint.h>

#define T_TOK 8192
#define H_DIM 1024
#define F_DIM 4096
#define E_NUM 8
#define N_SLOTS (T_TOK * 2)

// ---------------- scratch (device globals; no runtime allocation) ----------------
__device__ float g_probs[T_TOK * E_NUM];
__device__ float g_lse2[T_TOK];
__device__ int   g_tok_e[T_TOK * 2];
__device__ float g_tok_w[T_TOK * 2];
__device__ int   g_count[E_NUM];
__device__ int   g_off[E_NUM + 1];
__device__ int   g_cursor[E_NUM];
__device__ int   g_slot_tok[N_SLOTS];
__device__ float g_slot_w[N_SLOTS];

__device__ __half g_x16[(size_t)T_TOK * H_DIM];
__device__ __half g_wd16[(size_t)E_NUM * F_DIM * H_DIM];
__device__ __half g_h16[(size_t)N_SLOTS * F_DIM];   // 128 MB fp16 intermediate

// ---------------- PTX helpers ----------------
__device__ __forceinline__ uint32_t smem_u32(const void* p) {
    uint32_t a;
    asm("{ .reg .u64 t; cvta.to.shared.u64 t, %1; cvt.u32.u64 %0, t; }" : "=r"(a) : "l"(p));
    return a;
}
__device__ __forceinline__ void cp16(uint32_t dst, const void* src, uint32_t sz) {
    asm volatile("cp.async.cg.shared.global [%0], [%1], 16, %2;"
                 :: "r"(dst), "l"(__cvta_generic_to_global(src)), "r"(sz) : "memory");
}
__device__ __forceinline__ void cp_commit() {
    asm volatile("cp.async.commit_group;" ::: "memory");
}
__device__ __forceinline__ void ldsm4(uint32_t* r, uint32_t a) {
    asm volatile("ldmatrix.sync.aligned.m8n8.x4.shared.b16 {%0,%1,%2,%3}, [%4];"
                 : "=r"(r[0]), "=r"(r[1]), "=r"(r[2]), "=r"(r[3]) : "r"(a));
}
__device__ __forceinline__ void ldsm4t(uint32_t* r, uint32_t a) {
    asm volatile("ldmatrix.sync.aligned.m8n8.x4.trans.shared.b16 {%0,%1,%2,%3}, [%4];"
                 : "=r"(r[0]), "=r"(r[1]), "=r"(r[2]), "=r"(r[3]) : "r"(a));
}
__device__ __forceinline__ void mma_f16(float* c, const uint32_t* a, const uint32_t* b) {
    asm volatile("mma.sync.aligned.m16n8k16.row.col.f32.f16.f16.f32 "
                 "{%0,%1,%2,%3}, {%4,%5,%6,%7}, {%8,%9}, {%0,%1,%2,%3};"
                 : "+f"(c[0]), "+f"(c[1]), "+f"(c[2]), "+f"(c[3])
                 : "r"(a[0]), "r"(a[1]), "r"(a[2]), "r"(a[3]), "r"(b[0]), "r"(b[1]));
}
__device__ __forceinline__ float silu_mul(float g, float u) {
    return g / (1.f + __expf(-g)) * u;
}
__device__ __forceinline__ uint4 pack8(float4 a, float4 b) {
    union { __half2 h; uint32_t u; } p0, p1, p2, p3;
    p0.h = __floats2half2_rn(a.x, a.y); p1.h = __floats2half2_rn(a.z, a.w);
    p2.h = __floats2half2_rn(b.x, b.y); p3.h = __floats2half2_rn(b.z, b.w);
    return make_uint4(p0.u, p1.u, p2.u, p3.u);
}

// ---------------- init ----------------
__global__ void init_kernel(float* out, int n) {
    int tid = blockIdx.x * blockDim.x + threadIdx.x;
    if (tid < E_NUM) { g_count[tid] = 0; g_cursor[tid] = 0; }
    for (int i = tid; i < n; i += gridDim.x * blockDim.x) out[i] = 0.f;
}

// ---------------- fp32 -> fp16 conversion (wd only; overlapped with gemmA) ----------------
__global__ void conv_kernel(const float* __restrict__ s, __half* __restrict__ d, int n) {
    int i = (blockIdx.x * 256 + threadIdx.x) * 4;
    if (i >= n) return;
    float4 v = *(const float4*)(s + i);
    union { __half2 h[2]; uint2 u; } pk;
    pk.h[0] = __floats2half2_rn(v.x, v.y);
    pk.h[1] = __floats2half2_rn(v.z, v.w);
    *(uint2*)(d + i) = pk.u;
}

// ---------------- router: one warp per token (also emits x as fp16) ----------------
__global__ void router_kernel(const float* __restrict__ x, const float* __restrict__ gw) {
    __shared__ float sgw[H_DIM * E_NUM];
    for (int i = threadIdx.x; i < H_DIM * E_NUM; i += blockDim.x) sgw[i] = gw[i];
    __syncthreads();

    int warp = threadIdx.x >> 5;
    int lane = threadIdx.x & 31;
    int t = blockIdx.x * (blockDim.x >> 5) + warp;
    if (t >= T_TOK) return;

    const float* xr = x + (size_t)t * H_DIM;
    float acc[E_NUM];
#pragma unroll
    for (int e = 0; e < E_NUM; e++) acc[e] = 0.f;
    for (int h = lane; h < H_DIM; h += 32) {
        float xv = xr[h];
#pragma unroll
        for (int e = 0; e < E_NUM; e++) acc[e] += xv * sgw[h * E_NUM + e];
    }

    {
        __half* dx = g_x16 + (size_t)t * H_DIM;
#pragma unroll
        for (int k = 0; k < H_DIM / 4 / 32; k++) {
            int idx = (lane + k * 32) * 4;
            float4 v = *(const float4*)(xr + idx);
            union { __half2 h[2]; uint2 u; } pk;
            pk.h[0] = __floats2half2_rn(v.x, v.y);
            pk.h[1] = __floats2half2_rn(v.z, v.w);
            *(uint2*)(dx + idx) = pk.u;
        }
    }

#pragma unroll
    for (int off = 16; off; off >>= 1)
#pragma unroll
        for (int e = 0; e < E_NUM; e++) acc[e] += __shfl_xor_sync(0xffffffffu, acc[e], off);

    if (lane == 0) {
        float m = acc[0];
#pragma unroll
        for (int e = 1; e < E_NUM; e++) m = fmaxf(m, acc[e]);
        float p[E_NUM], s = 0.f;
#pragma unroll
        for (int e = 0; e < E_NUM; e++) { p[e] = expf(acc[e] - m); s += p[e]; }
        float lse = m + logf(s);
        g_lse2[t] = lse * lse;
        float inv = 1.f / s;
#pragma unroll
        for (int e = 0; e < E_NUM; e++) { p[e] *= inv; g_probs[t * E_NUM + e] = p[e]; }
        int i1 = 0;
#pragma unroll
        for (int e = 1; e < E_NUM; e++) if (p[e] > p[i1]) i1 = e;
        int i2 = (i1 == 0) ? 1 : 0;
#pragma unroll
        for (int e = 0; e < E_NUM; e++) if (e != i1 && p[e] > p[i2]) i2 = e;
        float w1 = p[i1], w2 = p[i2];
        float ws = 1.f / (w1 + w2);
        g_tok_e[2 * t + 0] = i1;  g_tok_w[2 * t + 0] = w1 * ws;
        g_tok_e[2 * t + 1] = i2;  g_tok_w[2 * t + 1] = w2 * ws;
        atomicAdd(&g_count[i1], 1);
        atomicAdd(&g_count[i2], 1);
    }
}

__global__ void offsets_kernel() {
    g_off[0] = 0;
    for (int e = 0; e < E_NUM; e++) g_off[e + 1] = g_off[e] + g_count[e];
}

__global__ void scatter_kernel() {
    int t = blockIdx.x * blockDim.x + threadIdx.x;
    if (t >= T_TOK) return;
#pragma unroll
    for (int k = 0; k < 2; k++) {
        int e = g_tok_e[2 * t + k];
        int pos = g_off[e] + atomicAdd(&g_cursor[e], 1);
        g_slot_tok[pos] = t;
        g_slot_w[pos] = g_tok_w[2 * t + k];
    }
}

__global__ void reduce_kernel(float* out, int out_size) {
    __shared__ float sp[256 * E_NUM];
    __shared__ float sl[256];
    int tid = threadIdx.x;
    float lp[E_NUM];
#pragma unroll
    for (int e = 0; e < E_NUM; e++) lp[e] = 0.f;
    float ll = 0.f;
    for (int t = tid; t < T_TOK; t += 256) {
#pragma unroll
        for (int e = 0; e < E_NUM; e++) lp[e] += g_probs[t * E_NUM + e];
        ll += g_lse2[t];
    }
#pragma unroll
    for (int e = 0; e < E_NUM; e++) sp[tid * E_NUM + e] = lp[e];
    sl[tid] = ll;
    __syncthreads();
    for (int s = 128; s; s >>= 1) {
        if (tid < s) {
#pragma unroll
            for (int e = 0; e < E_NUM; e++) sp[tid * E_NUM + e] += sp[(tid + s) * E_NUM + e];
            sl[tid] += sl[tid + s];
        }
        __syncthreads();
    }
    if (tid == 0) {
        float bal = 0.f;
        for (int e = 0; e < E_NUM; e++) {
            float frac = (float)g_count[e] / (float)(T_TOK * 2);
            float meanp = sp[e] / (float)T_TOK;
            bal += frac * meanp;
        }
        out[out_size - 2] = bal * (float)E_NUM;
        out[out_size - 1] = sl[0] / (float)T_TOK;
    }
}

// ================= pass A: h = silu(X Wg)*(X Wu), fp16 mma, 512 threads =============
// CTA 128M x 128N(gate)+128N(up), BK=32, warp tile 32x32, 3-stage pipeline.
// A via cp.async from g_x16; weights LDG'd fp32 + converted in-register + STS.
// SMEM strides (bytes): A rows 80, B rows 272.
#define STG_A 27648
#define SMEM_A_BYTES (512 + 3 * STG_A)
#define STG_B 27136
#define SMEM_B_BYTES (3 * STG_B)

__global__ void __launch_bounds__(512, 1)
gemmA_kernel(const float* __restrict__ wg, const float* __restrict__ wu) {
    int e = blockIdx.z;
    int cnt = g_count[e];
    int m0 = blockIdx.y * 128;
    if (m0 >= cnt) return;
    int base = g_off[e];
    int n0 = blockIdx.x * 128;

    extern __shared__ __align__(16) char dsm[];
    int* toks = (int*)dsm;
    uint32_t sb = smem_u32(dsm);

    int tid = threadIdx.x, wid = tid >> 5, lane = tid & 31;
    int gid = lane >> 2, tig = lane & 3;
    int mb = (wid & 3) * 32;
    int nb = (wid >> 2) * 32;

    if (tid < 128) {
        int idx = m0 + tid;
        toks[tid] = (idx < cnt) ? g_slot_tok[base + idx] : -1;
    }
    __syncthreads();

    const float* Wg = wg + (size_t)e * H_DIM * F_DIM + n0;
    const float* Wu = wu + (size_t)e * H_DIM * F_DIM + n0;

    int a_row = tid >> 2, a_j = tid & 3;
    int b_row = tid >> 4, b_j = tid & 15;   // weight tile: 32 k-rows x 16 16B-slots

    const int NCH = H_DIM / 32;  // 32

    float4 wr[4];   // gate lo/hi, up lo/hi (8 fp32 each matrix)
#define LDW(c) {                                                                       \
        size_t off = (size_t)((c) * 32 + b_row) * F_DIM + b_j * 8;                     \
        wr[0] = *(const float4*)(Wg + off); wr[1] = *(const float4*)(Wg + off + 4);    \
        wr[2] = *(const float4*)(Wu + off); wr[3] = *(const float4*)(Wu + off + 4); }
#define STW(s) {                                                                       \
        char* p = dsm + 512 + (s) * STG_A + b_row * 272 + b_j * 16;                    \
        *(uint4*)(p + 10240) = pack8(wr[0], wr[1]);                                    \
        *(uint4*)(p + 18944) = pack8(wr[2], wr[3]); }
#define ISSUE_A(c, s) {                                                                \
        int k0 = (c) * 32;                                                             \
        uint32_t stg_i = sb + 512 + (s) * STG_A;                                       \
        int tok = toks[a_row];                                                         \
        const __half* src = g_x16 + (size_t)(tok < 0 ? 0 : tok) * H_DIM + k0 + a_j * 8;\
        cp16(stg_i + a_row * 80 + a_j * 16, src, tok >= 0 ? 16u : 0u);                 \
        cp_commit(); }

    // prologue: stages 0,1 fully staged; wr holds w(2)
    LDW(0); STW(0);
    LDW(1); STW(1);
    ISSUE_A(0, 0);
    ISSUE_A(1, 1);
    LDW(2);

    float accG[2][4][4], accU[2][4][4];
#pragma unroll
    for (int mt = 0; mt < 2; mt++)
#pragma unroll
        for (int nt = 0; nt < 4; nt++)
#pragma unroll
            for (int i = 0; i < 4; i++) { accG[mt][nt][i] = 0.f; accU[mt][nt][i] = 0.f; }

    uint32_t aOff = (uint32_t)((mb + (lane & 15)) * 80 + (lane >> 4) * 16);
    uint32_t bOff = (uint32_t)((lane & 15) * 272 + (lane >> 4) * 16);

    for (int c = 0; c < NCH; c++) {
        if (c + 1 < NCH) asm volatile("cp.async.wait_group 1;" ::: "memory");
        else             asm volatile("cp.async.wait_group 0;" ::: "memory");
        __syncthreads();                      // stage c ready; slot (c+2)%3 free
        if (c + 2 < NCH) {
            STW((c + 2) % 3);                 // wr = w(c+2), loaded last iter
            ISSUE_A(c + 2, (c + 2) % 3);
        }
        if (c + 3 < NCH) LDW(c + 3);          // latency hidden by compute below
        uint32_t stg = sb + 512 + (c % 3) * STG_A;
#pragma unroll
        for (int ks = 0; ks < 2; ks++) {
            uint32_t af[2][4];
#pragma unroll
            for (int mt = 0; mt < 2; mt++)
                ldsm4(af[mt], stg + aOff + mt * 16 * 80 + ks * 32);
            uint32_t bg[2][4], bu[2][4];
#pragma unroll
            for (int pr = 0; pr < 2; pr++) {
                uint32_t co = (uint32_t)((nb + pr * 16) * 2 + ks * 16 * 272);
                ldsm4t(bg[pr], stg + 10240 + bOff + co);
                ldsm4t(bu[pr], stg + 18944 + bOff + co);
            }
#pragma unroll
            for (int pr = 0; pr < 2; pr++)
#pragma unroll
                for (int hn = 0; hn < 2; hn++) {
                    int nt = pr * 2 + hn;
#pragma unroll
                    for (int mt = 0; mt < 2; mt++) {
                        mma_f16(accG[mt][nt], af[mt], bg[pr] + hn * 2);
                        mma_f16(accU[mt][nt], af[mt], bu[pr] + hn * 2);
                    }
                }
        }
    }

    // epilogue: silu(gate)*up -> g_h16
#pragma unroll
    for (int mt = 0; mt < 2; mt++)
#pragma unroll
        for (int half = 0; half < 2; half++) {
            int r = m0 + mb + mt * 16 + gid + half * 8;
            if (r < cnt) {
                __half* hp = g_h16 + (size_t)(base + r) * F_DIM + n0 + nb + tig * 2;
#pragma unroll
                for (int nt = 0; nt < 4; nt++) {
                    float h0 = silu_mul(accG[mt][nt][half * 2 + 0], accU[mt][nt][half * 2 + 0]);
                    float h1 = silu_mul(accG[mt][nt][half * 2 + 1], accU[mt][nt][half * 2 + 1]);
                    *(__half2*)(hp + nt * 8) = __floats2half2_rn(h0, h1);
                }
            }
        }
#undef ISSUE_A
#undef LDW
#undef STW
}

// ================= pass B: out += w * (H1 Wd), fp16 mma, 512 threads (R7 config) =====
// CTA 128M x 256N, BK=32, warp tile 32x64. B rows 528B stride.
__global__ void __launch_bounds__(512, 1)
gemmB_kernel(float* __restrict__ out) {
    int e = blockIdx.z;
    int cnt = g_count[e];
    int m0 = blockIdx.y * 128;
    if (m0 >= cnt) return;
    int base = g_off[e];
    int n0 = blockIdx.x * 256;

    extern __shared__ __align__(16) char dsm[];
    uint32_t sb = smem_u32(dsm);

    int tid = threadIdx.x, wid = tid >> 5, lane = tid & 31;
    int gid = lane >> 2, tig = lane & 3;
    int mb = (wid & 3) * 32;
    int nb = (wid >> 2) * 64;

    const __half* Wd = g_wd16 + (size_t)e * F_DIM * H_DIM + n0;

    int a_row = tid >> 2, a_j = tid & 3;
    int b_row[2], b_j[2];
#pragma unroll
    for (int i = 0; i < 2; i++) { int i2 = tid + i * 512; b_row[i] = i2 >> 5; b_j[i] = i2 & 31; }

    const int NCH = F_DIM / 32;  // 128
#define ISSUE_B(c, s)                                                                  \
    {                                                                                  \
        int k0 = (c) * 32;                                                             \
        uint32_t stg_i = sb + (s) * STG_B;                                             \
        int r = m0 + a_row;                                                            \
        int ok = (r < cnt);                                                            \
        const __half* src = g_h16 + (size_t)(base + (ok ? r : 0)) * F_DIM + k0 + a_j * 8; \
        cp16(stg_i + a_row * 80 + a_j * 16, src, ok ? 16u : 0u);                       \
        _Pragma("unroll")                                                              \
        for (int i = 0; i < 2; i++) {                                                  \
            cp16(stg_i + 10240 + b_row[i] * 528 + b_j[i] * 16,                         \
                 Wd + (size_t)(k0 + b_row[i]) * H_DIM + b_j[i] * 8, 16u);              \
        }                                                                              \
        cp_commit();                                                                   \
    }

    ISSUE_B(0, 0);
    ISSUE_B(1, 1);

    float acc[2][8][4];
#pragma unroll
    for (int mt = 0; mt < 2; mt++)
#pragma unroll
        for (int nt = 0; nt < 8; nt++)
#pragma unroll
            for (int i = 0; i < 4; i++) acc[mt][nt][i] = 0.f;

    uint32_t aOff = (uint32_t)((mb + (lane & 15)) * 80 + (lane >> 4) * 16);
    uint32_t bOff = (uint32_t)((lane & 15) * 528 + (lane >> 4) * 16);

    for (int c = 0; c < NCH; c++) {
        if (c + 1 < NCH) asm volatile("cp.async.wait_group 1;" ::: "memory");
        else             asm volatile("cp.async.wait_group 0;" ::: "memory");
        __syncthreads();
        if (c + 2 < NCH) ISSUE_B(c + 2, (c + 2) % 3);
        uint32_t stg = sb + (c % 3) * STG_B;
#pragma unroll
        for (int ks = 0; ks < 2; ks++) {
            uint32_t af[2][4];
#pragma unroll
            for (int mt = 0; mt < 2; mt++)
                ldsm4(af[mt], stg + aOff + mt * 16 * 80 + ks * 32);
            uint32_t bf[4][4];
#pragma unroll
            for (int pr = 0; pr < 4; pr++) {
                uint32_t co = (uint32_t)((nb + pr * 16) * 2 + ks * 16 * 528);
                ldsm4t(bf[pr], stg + 10240 + bOff + co);
            }
#pragma unroll
            for (int pr = 0; pr < 4; pr++)
#pragma unroll
                for (int hn = 0; hn < 2; hn++) {
                    int nt = pr * 2 + hn;
#pragma unroll
                    for (int mt = 0; mt < 2; mt++)
                        mma_f16(acc[mt][nt], af[mt], bf[pr] + hn * 2);
                }
        }
    }

    // epilogue: weighted atomic combine
#pragma unroll
    for (int mt = 0; mt < 2; mt++)
#pragma unroll
        for (int half = 0; half < 2; half++) {
            int r = m0 + mb + mt * 16 + gid + half * 8;
            if (r < cnt) {
                int tok = g_slot_tok[base + r];
                float w = g_slot_w[base + r];
                float* op = out + (size_t)tok * H_DIM + n0 + nb + tig * 2;
#pragma unroll
                for (int nt = 0; nt < 8; nt++) {
                    atomicAdd(op + nt * 8 + 0, w * acc[mt][nt][half * 2 + 0]);
                    atomicAdd(op + nt * 8 + 1, w * acc[mt][nt][half * 2 + 1]);
                }
            }
        }
#undef ISSUE_B
}

// ---------------- launch (conv(wd) overlapped on side stream) ----------------
extern "C" void kernel_launch(void* const* d_in, const int* in_sizes, int n_in,
                              void* d_out, int out_size) {
    const float* x  = (const float*)d_in[0];
    const float* gw = (const float*)d_in[1];
    const float* wg = (const float*)d_in[2];
    const float* wu = (const float*)d_in[3];
    const float* wd = (const float*)d_in[4];
    float* out = (float*)d_out;

    static cudaStream_t s2 = nullptr;
    static cudaEvent_t e0 = nullptr, e2 = nullptr;
    if (s2 == nullptr) {
        cudaStreamCreateWithFlags(&s2, cudaStreamNonBlocking);
        cudaEventCreateWithFlags(&e0, cudaEventDisableTiming);
        cudaEventCreateWithFlags(&e2, cudaEventDisableTiming);
        cudaFuncSetAttribute(gemmA_kernel, cudaFuncAttributeMaxDynamicSharedMemorySize, SMEM_A_BYTES);
        cudaFuncSetAttribute(gemmB_kernel, cudaFuncAttributeMaxDynamicSharedMemorySize, SMEM_B_BYTES);
    }

    __half* dd;
    cudaGetSymbolAddress((void**)&dd, g_wd16);
    const int NW = E_NUM * H_DIM * F_DIM;

    // fork: wd conversion runs alongside router chain + gemmA
    cudaEventRecord(e0, 0);
    cudaStreamWaitEvent(s2, e0, 0);
    conv_kernel<<<NW / 1024, 256, 0, s2>>>(wd, dd, NW);
    cudaEventRecord(e2, s2);

    // main: init -> router chain -> gemmA (weights converted in-kernel)
    init_kernel<<<512, 256>>>(out, out_size);
    router_kernel<<<T_TOK / 8, 256>>>(x, gw);   // also writes g_x16
    offsets_kernel<<<1, 1>>>();
    scatter_kernel<<<T_TOK / 256, 256>>>();
    reduce_kernel<<<1, 256>>>(out, out_size);

    dim3 gA(F_DIM / 128, N_SLOTS / 128, E_NUM);
    gemmA_kernel<<<gA, 512, SMEM_A_BYTES>>>(wg, wu);

    // join wd conversion, run gemmB
    cudaStreamWaitEvent(0, e2, 0);
    dim3 gB(H_DIM / 256, N_SLOTS / 128, E_NUM);
    gemmB_kernel<<<gB, 512, SMEM_B_BYTES>>>(out);
}

// round 11
// speedup vs baseline: 1.0790x; 1.0790x over previous
#include <cuda_runtime.h>
#include <cuda_fp16.h>
#include <math.h>
#include <stdint.h>

#define T_TOK 8192
#define H_DIM 1024
#define F_DIM 4096
#define E_NUM 8
#define N_SLOTS (T_TOK * 2)

// ---------------- scratch (device globals; no runtime allocation) ----------------
__device__ float g_probs[T_TOK * E_NUM];
__device__ float g_lse2[T_TOK];
__device__ int   g_tok_e[T_TOK * 2];
__device__ float g_tok_w[T_TOK * 2];
__device__ int   g_count[E_NUM];
__device__ int   g_off[E_NUM + 1];
__device__ int   g_cursor[E_NUM];
__device__ int   g_slot_tok[N_SLOTS];
__device__ float g_slot_w[N_SLOTS];

__device__ __half g_x16[(size_t)T_TOK * H_DIM];
__device__ __half g_wg16[(size_t)E_NUM * H_DIM * F_DIM];
__device__ __half g_wu16[(size_t)E_NUM * H_DIM * F_DIM];
__device__ __half g_wd16[(size_t)E_NUM * F_DIM * H_DIM];
__device__ __half g_h16[(size_t)N_SLOTS * F_DIM];   // 128 MB fp16 intermediate

// ---------------- PTX helpers ----------------
__device__ __forceinline__ uint32_t smem_u32(const void* p) {
    uint32_t a;
    asm("{ .reg .u64 t; cvta.to.shared.u64 t, %1; cvt.u32.u64 %0, t; }" : "=r"(a) : "l"(p));
    return a;
}
__device__ __forceinline__ void cp16(uint32_t dst, const void* src, uint32_t sz) {
    asm volatile("cp.async.cg.shared.global [%0], [%1], 16, %2;"
                 :: "r"(dst), "l"(__cvta_generic_to_global(src)), "r"(sz) : "memory");
}
__device__ __forceinline__ void cp_commit() {
    asm volatile("cp.async.commit_group;" ::: "memory");
}
__device__ __forceinline__ void ldsm4(uint32_t* r, uint32_t a) {
    asm volatile("ldmatrix.sync.aligned.m8n8.x4.shared.b16 {%0,%1,%2,%3}, [%4];"
                 : "=r"(r[0]), "=r"(r[1]), "=r"(r[2]), "=r"(r[3]) : "r"(a));
}
__device__ __forceinline__ void ldsm4t(uint32_t* r, uint32_t a) {
    asm volatile("ldmatrix.sync.aligned.m8n8.x4.trans.shared.b16 {%0,%1,%2,%3}, [%4];"
                 : "=r"(r[0]), "=r"(r[1]), "=r"(r[2]), "=r"(r[3]) : "r"(a));
}
__device__ __forceinline__ void mma_f16(float* c, const uint32_t* a, const uint32_t* b) {
    asm volatile("mma.sync.aligned.m16n8k16.row.col.f32.f16.f16.f32 "
                 "{%0,%1,%2,%3}, {%4,%5,%6,%7}, {%8,%9}, {%0,%1,%2,%3};"
                 : "+f"(c[0]), "+f"(c[1]), "+f"(c[2]), "+f"(c[3])
                 : "r"(a[0]), "r"(a[1]), "r"(a[2]), "r"(a[3]), "r"(b[0]), "r"(b[1]));
}
__device__ __forceinline__ float silu_mul(float g, float u) {
    return g / (1.f + __expf(-g)) * u;
}

// ---------------- init ----------------
__global__ void init_kernel(float* out, int n) {
    int tid = blockIdx.x * blockDim.x + threadIdx.x;
    if (tid < E_NUM) { g_count[tid] = 0; g_cursor[tid] = 0; }
    for (int i = tid; i < n; i += gridDim.x * blockDim.x) out[i] = 0.f;
}

// ---------------- fp32 -> fp16 conversion (all 3 weight tensors, one launch) ----------------
__global__ void conv3_kernel(const float* __restrict__ wg, const float* __restrict__ wu,
                             const float* __restrict__ wd,
                             __half* __restrict__ dg, __half* __restrict__ du,
                             __half* __restrict__ dd, int n) {
    const float* s = (blockIdx.y == 0) ? wg : (blockIdx.y == 1) ? wu : wd;
    __half* d = (blockIdx.y == 0) ? dg : (blockIdx.y == 1) ? du : dd;
    int i = (blockIdx.x * 256 + threadIdx.x) * 4;
    if (i >= n) return;
    float4 v = *(const float4*)(s + i);
    union { __half2 h[2]; uint2 u; } pk;
    pk.h[0] = __floats2half2_rn(v.x, v.y);
    pk.h[1] = __floats2half2_rn(v.z, v.w);
    *(uint2*)(d + i) = pk.u;
}

// ---------------- router: one warp per token (also emits x as fp16) ----------------
__global__ void router_kernel(const float* __restrict__ x, const float* __restrict__ gw) {
    __shared__ float sgw[H_DIM * E_NUM];
    for (int i = threadIdx.x; i < H_DIM * E_NUM; i += blockDim.x) sgw[i] = gw[i];
    __syncthreads();

    int warp = threadIdx.x >> 5;
    int lane = threadIdx.x & 31;
    int t = blockIdx.x * (blockDim.x >> 5) + warp;
    if (t >= T_TOK) return;

    const float* xr = x + (size_t)t * H_DIM;
    float acc[E_NUM];
#pragma unroll
    for (int e = 0; e < E_NUM; e++) acc[e] = 0.f;
    for (int h = lane; h < H_DIM; h += 32) {
        float xv = xr[h];
#pragma unroll
        for (int e = 0; e < E_NUM; e++) acc[e] += xv * sgw[h * E_NUM + e];
    }

    {
        __half* dx = g_x16 + (size_t)t * H_DIM;
#pragma unroll
        for (int k = 0; k < H_DIM / 4 / 32; k++) {
            int idx = (lane + k * 32) * 4;
            float4 v = *(const float4*)(xr + idx);
            union { __half2 h[2]; uint2 u; } pk;
            pk.h[0] = __floats2half2_rn(v.x, v.y);
            pk.h[1] = __floats2half2_rn(v.z, v.w);
            *(uint2*)(dx + idx) = pk.u;
        }
    }

#pragma unroll
    for (int off = 16; off; off >>= 1)
#pragma unroll
        for (int e = 0; e < E_NUM; e++) acc[e] += __shfl_xor_sync(0xffffffffu, acc[e], off);

    if (lane == 0) {
        float m = acc[0];
#pragma unroll
        for (int e = 1; e < E_NUM; e++) m = fmaxf(m, acc[e]);
        float p[E_NUM], s = 0.f;
#pragma unroll
        for (int e = 0; e < E_NUM; e++) { p[e] = expf(acc[e] - m); s += p[e]; }
        float lse = m + logf(s);
        g_lse2[t] = lse * lse;
        float inv = 1.f / s;
#pragma unroll
        for (int e = 0; e < E_NUM; e++) { p[e] *= inv; g_probs[t * E_NUM + e] = p[e]; }
        int i1 = 0;
#pragma unroll
        for (int e = 1; e < E_NUM; e++) if (p[e] > p[i1]) i1 = e;
        int i2 = (i1 == 0) ? 1 : 0;
#pragma unroll
        for (int e = 0; e < E_NUM; e++) if (e != i1 && p[e] > p[i2]) i2 = e;
        float w1 = p[i1], w2 = p[i2];
        float ws = 1.f / (w1 + w2);
        g_tok_e[2 * t + 0] = i1;  g_tok_w[2 * t + 0] = w1 * ws;
        g_tok_e[2 * t + 1] = i2;  g_tok_w[2 * t + 1] = w2 * ws;
        atomicAdd(&g_count[i1], 1);
        atomicAdd(&g_count[i2], 1);
    }
}

__global__ void offsets_kernel() {
    g_off[0] = 0;
    for (int e = 0; e < E_NUM; e++) g_off[e + 1] = g_off[e] + g_count[e];
}

__global__ void scatter_kernel() {
    int t = blockIdx.x * blockDim.x + threadIdx.x;
    if (t >= T_TOK) return;
#pragma unroll
    for (int k = 0; k < 2; k++) {
        int e = g_tok_e[2 * t + k];
        int pos = g_off[e] + atomicAdd(&g_cursor[e], 1);
        g_slot_tok[pos] = t;
        g_slot_w[pos] = g_tok_w[2 * t + k];
    }
}

__global__ void reduce_kernel(float* out, int out_size) {
    __shared__ float sp[256 * E_NUM];
    __shared__ float sl[256];
    int tid = threadIdx.x;
    float lp[E_NUM];
#pragma unroll
    for (int e = 0; e < E_NUM; e++) lp[e] = 0.f;
    float ll = 0.f;
    for (int t = tid; t < T_TOK; t += 256) {
#pragma unroll
        for (int e = 0; e < E_NUM; e++) lp[e] += g_probs[t * E_NUM + e];
        ll += g_lse2[t];
    }
#pragma unroll
    for (int e = 0; e < E_NUM; e++) sp[tid * E_NUM + e] = lp[e];
    sl[tid] = ll;
    __syncthreads();
    for (int s = 128; s; s >>= 1) {
        if (tid < s) {
#pragma unroll
            for (int e = 0; e < E_NUM; e++) sp[tid * E_NUM + e] += sp[(tid + s) * E_NUM + e];
            sl[tid] += sl[tid + s];
        }
        __syncthreads();
    }
    if (tid == 0) {
        float bal = 0.f;
        for (int e = 0; e < E_NUM; e++) {
            float frac = (float)g_count[e] / (float)(T_TOK * 2);
            float meanp = sp[e] / (float)T_TOK;
            bal += frac * meanp;
        }
        out[out_size - 2] = bal * (float)E_NUM;
        out[out_size - 1] = sl[0] / (float)T_TOK;
    }
}

// ================= pass A: h = silu(X Wg)*(X Wu), fp16 mma, 512 threads (R7) ==========
// CTA 128M x 128N(gate)+128N(up), BK=32, 16 warps, warp tile 32x32.
// SMEM strides (bytes): A rows 80, B rows 272. 3-stage cp.async, 1 sync/iter.
#define STG_A 27648
#define SMEM_A_BYTES (512 + 3 * STG_A)

__global__ void __launch_bounds__(512, 1)
gemmA_kernel() {
    int e = blockIdx.z;
    int cnt = g_count[e];
    int m0 = blockIdx.y * 128;
    if (m0 >= cnt) return;
    int base = g_off[e];
    int n0 = blockIdx.x * 128;

    extern __shared__ __align__(16) char dsm[];
    int* toks = (int*)dsm;
    uint32_t sb = smem_u32(dsm);

    int tid = threadIdx.x, wid = tid >> 5, lane = tid & 31;
    int gid = lane >> 2, tig = lane & 3;
    int mb = (wid & 3) * 32;
    int nb = (wid >> 2) * 32;

    if (tid < 128) {
        int idx = m0 + tid;
        toks[tid] = (idx < cnt) ? g_slot_tok[base + idx] : -1;
    }
    __syncthreads();

    const __half* Wg = g_wg16 + (size_t)e * H_DIM * F_DIM + n0;
    const __half* Wu = g_wu16 + (size_t)e * H_DIM * F_DIM + n0;

    int a_row = tid >> 2, a_j = tid & 3;
    int b_row = tid >> 4, b_j = tid & 15;

    const int NCH = H_DIM / 32;  // 32
#define ISSUE_A(c, s)                                                                  \
    {                                                                                  \
        int k0 = (c) * 32;                                                             \
        uint32_t stg_i = sb + 512 + (s) * STG_A;                                       \
        int tok = toks[a_row];                                                         \
        const __half* src = g_x16 + (size_t)(tok < 0 ? 0 : tok) * H_DIM + k0 + a_j * 8;\
        cp16(stg_i + a_row * 80 + a_j * 16, src, tok >= 0 ? 16u : 0u);                 \
        cp16(stg_i + 10240 + b_row * 272 + b_j * 16,                                   \
             Wg + (size_t)(k0 + b_row) * F_DIM + b_j * 8, 16u);                        \
        cp16(stg_i + 18944 + b_row * 272 + b_j * 16,                                   \
             Wu + (size_t)(k0 + b_row) * F_DIM + b_j * 8, 16u);                        \
        cp_commit();                                                                   \
    }

    ISSUE_A(0, 0);
    ISSUE_A(1, 1);

    float accG[2][4][4], accU[2][4][4];
#pragma unroll
    for (int mt = 0; mt < 2; mt++)
#pragma unroll
        for (int nt = 0; nt < 4; nt++)
#pragma unroll
            for (int i = 0; i < 4; i++) { accG[mt][nt][i] = 0.f; accU[mt][nt][i] = 0.f; }

    uint32_t aOff = (uint32_t)((mb + (lane & 15)) * 80 + (lane >> 4) * 16);
    uint32_t bOff = (uint32_t)((lane & 15) * 272 + (lane >> 4) * 16);

    for (int c = 0; c < NCH; c++) {
        if (c + 1 < NCH) asm volatile("cp.async.wait_group 1;" ::: "memory");
        else             asm volatile("cp.async.wait_group 0;" ::: "memory");
        __syncthreads();
        if (c + 2 < NCH) ISSUE_A(c + 2, (c + 2) % 3);
        uint32_t stg = sb + 512 + (c % 3) * STG_A;
#pragma unroll
        for (int ks = 0; ks < 2; ks++) {
            uint32_t af[2][4];
#pragma unroll
            for (int mt = 0; mt < 2; mt++)
                ldsm4(af[mt], stg + aOff + mt * 16 * 80 + ks * 32);
            uint32_t bg[2][4], bu[2][4];
#pragma unroll
            for (int pr = 0; pr < 2; pr++) {
                uint32_t co = (uint32_t)((nb + pr * 16) * 2 + ks * 16 * 272);
                ldsm4t(bg[pr], stg + 10240 + bOff + co);
                ldsm4t(bu[pr], stg + 18944 + bOff + co);
            }
#pragma unroll
            for (int pr = 0; pr < 2; pr++)
#pragma unroll
                for (int hn = 0; hn < 2; hn++) {
                    int nt = pr * 2 + hn;
#pragma unroll
                    for (int mt = 0; mt < 2; mt++) {
                        mma_f16(accG[mt][nt], af[mt], bg[pr] + hn * 2);
                        mma_f16(accU[mt][nt], af[mt], bu[pr] + hn * 2);
                    }
                }
        }
    }

    // epilogue: silu(gate)*up -> g_h16
#pragma unroll
    for (int mt = 0; mt < 2; mt++)
#pragma unroll
        for (int half = 0; half < 2; half++) {
            int r = m0 + mb + mt * 16 + gid + half * 8;
            if (r < cnt) {
                __half* hp = g_h16 + (size_t)(base + r) * F_DIM + n0 + nb + tig * 2;
#pragma unroll
                for (int nt = 0; nt < 4; nt++) {
                    float h0 = silu_mul(accG[mt][nt][half * 2 + 0], accU[mt][nt][half * 2 + 0]);
                    float h1 = silu_mul(accG[mt][nt][half * 2 + 1], accU[mt][nt][half * 2 + 1]);
                    *(__half2*)(hp + nt * 8) = __floats2half2_rn(h0, h1);
                }
            }
        }
#undef ISSUE_A
}

// ================= pass B: out += w * (H1 Wd), fp16 mma, 256 threads, 2 CTA/SM =======
// CTA 128M x 128N, BK=32, 8 warps (4m x 2n), warp tile 32x64 (same shape as R7).
// 1024 working CTAs on 296 resident slots -> fine-grained tail.
#define STG_B 18944
#define SMEM_B_BYTES (3 * STG_B)

__global__ void __launch_bounds__(256, 2)
gemmB_kernel(float* __restrict__ out) {
    int e = blockIdx.z;
    int cnt = g_count[e];
    int m0 = blockIdx.y * 128;
    if (m0 >= cnt) return;
    int base = g_off[e];
    int n0 = blockIdx.x * 128;

    extern __shared__ __align__(16) char dsm[];
    uint32_t sb = smem_u32(dsm);

    int tid = threadIdx.x, wid = tid >> 5, lane = tid & 31;
    int gid = lane >> 2, tig = lane & 3;
    int mb = (wid & 3) * 32;
    int nb = (wid >> 2) * 64;

    const __half* Wd = g_wd16 + (size_t)e * F_DIM * H_DIM + n0;

    // staging: A 128r x 4 slots (512 slots), B 32r x 16 slots (512 slots); 2 cp each
    int a_row[2], a_j[2], b_row[2], b_j[2];
#pragma unroll
    for (int i = 0; i < 2; i++) {
        int i2 = tid + i * 256;
        a_row[i] = i2 >> 2;  a_j[i] = i2 & 3;
        b_row[i] = i2 >> 4;  b_j[i] = i2 & 15;
    }

    const int NCH = F_DIM / 32;  // 128
#define ISSUE_B(c, s)                                                                  \
    {                                                                                  \
        int k0 = (c) * 32;                                                             \
        uint32_t stg_i = sb + (s) * STG_B;                                             \
        _Pragma("unroll")                                                              \
        for (int i = 0; i < 2; i++) {                                                  \
            int r = m0 + a_row[i];                                                     \
            int ok = (r < cnt);                                                        \
            const __half* src = g_h16 + (size_t)(base + (ok ? r : 0)) * F_DIM + k0 + a_j[i] * 8; \
            cp16(stg_i + a_row[i] * 80 + a_j[i] * 16, src, ok ? 16u : 0u);             \
            cp16(stg_i + 10240 + b_row[i] * 272 + b_j[i] * 16,                         \
                 Wd + (size_t)(k0 + b_row[i]) * H_DIM + b_j[i] * 8, 16u);              \
        }                                                                              \
        cp_commit();                                                                   \
    }

    ISSUE_B(0, 0);
    ISSUE_B(1, 1);

    float acc[2][8][4];
#pragma unroll
    for (int mt = 0; mt < 2; mt++)
#pragma unroll
        for (int nt = 0; nt < 8; nt++)
#pragma unroll
            for (int i = 0; i < 4; i++) acc[mt][nt][i] = 0.f;

    uint32_t aOff = (uint32_t)((mb + (lane & 15)) * 80 + (lane >> 4) * 16);
    uint32_t bOff = (uint32_t)((lane & 15) * 272 + (lane >> 4) * 16);

    for (int c = 0; c < NCH; c++) {
        if (c + 1 < NCH) asm volatile("cp.async.wait_group 1;" ::: "memory");
        else             asm volatile("cp.async.wait_group 0;" ::: "memory");
        __syncthreads();
        if (c + 2 < NCH) ISSUE_B(c + 2, (c + 2) % 3);
        uint32_t stg = sb + (c % 3) * STG_B;
#pragma unroll
        for (int ks = 0; ks < 2; ks++) {
            uint32_t af[2][4];
#pragma unroll
            for (int mt = 0; mt < 2; mt++)
                ldsm4(af[mt], stg + aOff + mt * 16 * 80 + ks * 32);
            uint32_t bf[4][4];
#pragma unroll
            for (int pr = 0; pr < 4; pr++) {
                uint32_t co = (uint32_t)((nb + pr * 16) * 2 + ks * 16 * 272);
                ldsm4t(bf[pr], stg + 10240 + bOff + co);
            }
#pragma unroll
            for (int pr = 0; pr < 4; pr++)
#pragma unroll
                for (int hn = 0; hn < 2; hn++) {
                    int nt = pr * 2 + hn;
#pragma unroll
                    for (int mt = 0; mt < 2; mt++)
                        mma_f16(acc[mt][nt], af[mt], bf[pr] + hn * 2);
                }
        }
    }

    // epilogue: weighted atomic combine
#pragma unroll
    for (int mt = 0; mt < 2; mt++)
#pragma unroll
        for (int half = 0; half < 2; half++) {
            int r = m0 + mb + mt * 16 + gid + half * 8;
            if (r < cnt) {
                int tok = g_slot_tok[base + r];
                float w = g_slot_w[base + r];
                float* op = out + (size_t)tok * H_DIM + n0 + nb + tig * 2;
#pragma unroll
                for (int nt = 0; nt < 8; nt++) {
                    atomicAdd(op + nt * 8 + 0, w * acc[mt][nt][half * 2 + 0]);
                    atomicAdd(op + nt * 8 + 1, w * acc[mt][nt][half * 2 + 1]);
                }
            }
        }
#undef ISSUE_B
}

// ---------------- launch (single stream, R7 structure) ----------------
extern "C" void kernel_launch(void* const* d_in, const int* in_sizes, int n_in,
                              void* d_out, int out_size) {
    const float* x  = (const float*)d_in[0];
    const float* gw = (const float*)d_in[1];
    const float* wg = (const float*)d_in[2];
    const float* wu = (const float*)d_in[3];
    const float* wd = (const float*)d_in[4];
    float* out = (float*)d_out;

    cudaFuncSetAttribute(gemmA_kernel, cudaFuncAttributeMaxDynamicSharedMemorySize, SMEM_A_BYTES);
    cudaFuncSetAttribute(gemmB_kernel, cudaFuncAttributeMaxDynamicSharedMemorySize, SMEM_B_BYTES);

    init_kernel<<<512, 256>>>(out, out_size);

    __half* dg; __half* du; __half* dd;
    cudaGetSymbolAddress((void**)&dg, g_wg16);
    cudaGetSymbolAddress((void**)&du, g_wu16);
    cudaGetSymbolAddress((void**)&dd, g_wd16);
    const int NW = E_NUM * H_DIM * F_DIM;
    dim3 gC(NW / 1024, 3);
    conv3_kernel<<<gC, 256>>>(wg, wu, wd, dg, du, dd, NW);

    router_kernel<<<T_TOK / 8, 256>>>(x, gw);   // also writes g_x16
    offsets_kernel<<<1, 1>>>();
    scatter_kernel<<<T_TOK / 256, 256>>>();
    reduce_kernel<<<1, 256>>>(out, out_size);

    dim3 gA(F_DIM / 128, N_SLOTS / 128, E_NUM);
    gemmA_kernel<<<gA, 512, SMEM_A_BYTES>>>();

    dim3 gB(H_DIM / 128, N_SLOTS / 128, E_NUM);
    gemmB_kernel<<<gB, 256, SMEM_B_BYTES>>>(out);
}

// round 12
// speedup vs baseline: 1.1899x; 1.1028x over previous
#include <cuda_runtime.h>
#include <cuda_fp16.h>
#include <math.h>
#include <stdint.h>

#define T_TOK 8192
#define H_DIM 1024
#define F_DIM 4096
#define E_NUM 8
#define N_SLOTS (T_TOK * 2)

// ---------------- scratch (device globals; no runtime allocation) ----------------
__device__ float g_probs[T_TOK * E_NUM];
__device__ float g_lse2[T_TOK];
__device__ int   g_tok_e[T_TOK * 2];
__device__ float g_tok_w[T_TOK * 2];
__device__ int   g_count[E_NUM];
__device__ int   g_off[E_NUM + 1];
__device__ int   g_cursor[E_NUM];
__device__ int   g_slot_tok[N_SLOTS];
__device__ float g_slot_w[N_SLOTS];

__device__ __half g_x16[(size_t)T_TOK * H_DIM];
__device__ __half g_wg16[(size_t)E_NUM * H_DIM * F_DIM];
__device__ __half g_wu16[(size_t)E_NUM * H_DIM * F_DIM];
__device__ __half g_wd16[(size_t)E_NUM * F_DIM * H_DIM];
__device__ __half g_h16[(size_t)N_SLOTS * F_DIM];   // 128 MB fp16 intermediate

// ---------------- PTX helpers ----------------
__device__ __forceinline__ uint32_t smem_u32(const void* p) {
    uint32_t a;
    asm("{ .reg .u64 t; cvta.to.shared.u64 t, %1; cvt.u32.u64 %0, t; }" : "=r"(a) : "l"(p));
    return a;
}
__device__ __forceinline__ void cp16(uint32_t dst, const void* src, uint32_t sz) {
    asm volatile("cp.async.cg.shared.global [%0], [%1], 16, %2;"
                 :: "r"(dst), "l"(__cvta_generic_to_global(src)), "r"(sz) : "memory");
}
__device__ __forceinline__ void cp_commit() {
    asm volatile("cp.async.commit_group;" ::: "memory");
}
__device__ __forceinline__ void ldsm4(uint32_t* r, uint32_t a) {
    asm volatile("ldmatrix.sync.aligned.m8n8.x4.shared.b16 {%0,%1,%2,%3}, [%4];"
                 : "=r"(r[0]), "=r"(r[1]), "=r"(r[2]), "=r"(r[3]) : "r"(a));
}
__device__ __forceinline__ void ldsm4t(uint32_t* r, uint32_t a) {
    asm volatile("ldmatrix.sync.aligned.m8n8.x4.trans.shared.b16 {%0,%1,%2,%3}, [%4];"
                 : "=r"(r[0]), "=r"(r[1]), "=r"(r[2]), "=r"(r[3]) : "r"(a));
}
__device__ __forceinline__ void mma_f16(float* c, const uint32_t* a, const uint32_t* b) {
    asm volatile("mma.sync.aligned.m16n8k16.row.col.f32.f16.f16.f32 "
                 "{%0,%1,%2,%3}, {%4,%5,%6,%7}, {%8,%9}, {%0,%1,%2,%3};"
                 : "+f"(c[0]), "+f"(c[1]), "+f"(c[2]), "+f"(c[3])
                 : "r"(a[0]), "r"(a[1]), "r"(a[2]), "r"(a[3]), "r"(b[0]), "r"(b[1]));
}
__device__ __forceinline__ float silu_mul(float g, float u) {
    return g / (1.f + __expf(-g)) * u;
}

// ---------------- init ----------------
__global__ void init_kernel(float* out, int n) {
    int tid = blockIdx.x * blockDim.x + threadIdx.x;
    if (tid < E_NUM) { g_count[tid] = 0; g_cursor[tid] = 0; }
    for (int i = tid; i < n; i += gridDim.x * blockDim.x) out[i] = 0.f;
}

// ---------------- fp32 -> fp16 conversion (all 3 weight tensors, one launch) ----------------
__global__ void conv3_kernel(const float* __restrict__ wg, const float* __restrict__ wu,
                             const float* __restrict__ wd,
                             __half* __restrict__ dg, __half* __restrict__ du,
                             __half* __restrict__ dd, int n) {
    const float* s = (blockIdx.y == 0) ? wg : (blockIdx.y == 1) ? wu : wd;
    __half* d = (blockIdx.y == 0) ? dg : (blockIdx.y == 1) ? du : dd;
    int i = (blockIdx.x * 256 + threadIdx.x) * 4;
    if (i >= n) return;
    float4 v = *(const float4*)(s + i);
    union { __half2 h[2]; uint2 u; } pk;
    pk.h[0] = __floats2half2_rn(v.x, v.y);
    pk.h[1] = __floats2half2_rn(v.z, v.w);
    *(uint2*)(d + i) = pk.u;
}

// ---------------- router: one warp per token (also emits x as fp16) ----------------
__global__ void router_kernel(const float* __restrict__ x, const float* __restrict__ gw) {
    __shared__ float sgw[H_DIM * E_NUM];
    for (int i = threadIdx.x; i < H_DIM * E_NUM; i += blockDim.x) sgw[i] = gw[i];
    __syncthreads();

    int warp = threadIdx.x >> 5;
    int lane = threadIdx.x & 31;
    int t = blockIdx.x * (blockDim.x >> 5) + warp;
    if (t >= T_TOK) return;

    const float* xr = x + (size_t)t * H_DIM;
    float acc[E_NUM];
#pragma unroll
    for (int e = 0; e < E_NUM; e++) acc[e] = 0.f;
    for (int h = lane; h < H_DIM; h += 32) {
        float xv = xr[h];
#pragma unroll
        for (int e = 0; e < E_NUM; e++) acc[e] += xv * sgw[h * E_NUM + e];
    }

    {
        __half* dx = g_x16 + (size_t)t * H_DIM;
#pragma unroll
        for (int k = 0; k < H_DIM / 4 / 32; k++) {
            int idx = (lane + k * 32) * 4;
            float4 v = *(const float4*)(xr + idx);
            union { __half2 h[2]; uint2 u; } pk;
            pk.h[0] = __floats2half2_rn(v.x, v.y);
            pk.h[1] = __floats2half2_rn(v.z, v.w);
            *(uint2*)(dx + idx) = pk.u;
        }
    }

#pragma unroll
    for (int off = 16; off; off >>= 1)
#pragma unroll
        for (int e = 0; e < E_NUM; e++) acc[e] += __shfl_xor_sync(0xffffffffu, acc[e], off);

    if (lane == 0) {
        float m = acc[0];
#pragma unroll
        for (int e = 1; e < E_NUM; e++) m = fmaxf(m, acc[e]);
        float p[E_NUM], s = 0.f;
#pragma unroll
        for (int e = 0; e < E_NUM; e++) { p[e] = expf(acc[e] - m); s += p[e]; }
        float lse = m + logf(s);
        g_lse2[t] = lse * lse;
        float inv = 1.f / s;
#pragma unroll
        for (int e = 0; e < E_NUM; e++) { p[e] *= inv; g_probs[t * E_NUM + e] = p[e]; }
        int i1 = 0;
#pragma unroll
        for (int e = 1; e < E_NUM; e++) if (p[e] > p[i1]) i1 = e;
        int i2 = (i1 == 0) ? 1 : 0;
#pragma unroll
        for (int e = 0; e < E_NUM; e++) if (e != i1 && p[e] > p[i2]) i2 = e;
        float w1 = p[i1], w2 = p[i2];
        float ws = 1.f / (w1 + w2);
        g_tok_e[2 * t + 0] = i1;  g_tok_w[2 * t + 0] = w1 * ws;
        g_tok_e[2 * t + 1] = i2;  g_tok_w[2 * t + 1] = w2 * ws;
        atomicAdd(&g_count[i1], 1);
        atomicAdd(&g_count[i2], 1);
    }
}

// ---------------- scatter (computes offsets locally; block 0 publishes g_off) ----------------
__global__ void scatter_kernel() {
    int off[E_NUM + 1];
    off[0] = 0;
#pragma unroll
    for (int e = 0; e < E_NUM; e++) off[e + 1] = off[e] + g_count[e];

    int t = blockIdx.x * blockDim.x + threadIdx.x;
    if (blockIdx.x == 0 && threadIdx.x == 0) {
#pragma unroll
        for (int e = 0; e <= E_NUM; e++) g_off[e] = off[e];
    }
    if (t >= T_TOK) return;
#pragma unroll
    for (int k = 0; k < 2; k++) {
        int e = g_tok_e[2 * t + k];
        int pos = off[e] + atomicAdd(&g_cursor[e], 1);
        g_slot_tok[pos] = t;
        g_slot_w[pos] = g_tok_w[2 * t + k];
    }
}

__global__ void reduce_kernel(float* out, int out_size) {
    __shared__ float sp[256 * E_NUM];
    __shared__ float sl[256];
    int tid = threadIdx.x;
    float lp[E_NUM];
#pragma unroll
    for (int e = 0; e < E_NUM; e++) lp[e] = 0.f;
    float ll = 0.f;
    for (int t = tid; t < T_TOK; t += 256) {
#pragma unroll
        for (int e = 0; e < E_NUM; e++) lp[e] += g_probs[t * E_NUM + e];
        ll += g_lse2[t];
    }
#pragma unroll
    for (int e = 0; e < E_NUM; e++) sp[tid * E_NUM + e] = lp[e];
    sl[tid] = ll;
    __syncthreads();
    for (int s = 128; s; s >>= 1) {
        if (tid < s) {
#pragma unroll
            for (int e = 0; e < E_NUM; e++) sp[tid * E_NUM + e] += sp[(tid + s) * E_NUM + e];
            sl[tid] += sl[tid + s];
        }
        __syncthreads();
    }
    if (tid == 0) {
        float bal = 0.f;
        for (int e = 0; e < E_NUM; e++) {
            float frac = (float)g_count[e] / (float)(T_TOK * 2);
            float meanp = sp[e] / (float)T_TOK;
            bal += frac * meanp;
        }
        out[out_size - 2] = bal * (float)E_NUM;
        out[out_size - 1] = sl[0] / (float)T_TOK;
    }
}

// ================= pass A: h = silu(X Wg)*(X Wu), fp16 mma, 256 threads, 2 CTA/SM =====
// CTA 128M x 64N(gate)+64N(up), BK=32, 8 warps (4m x 2n), warp tile 32x32 per matrix.
// SMEM strides (bytes): A rows 80, B rows 144. 3-stage cp.async, 1 sync/iter.
#define STG_A 19456
#define SMEM_A_BYTES (512 + 3 * STG_A)

__global__ void __launch_bounds__(256, 2)
gemmA_kernel() {
    int e = blockIdx.z;
    int cnt = g_count[e];
    int m0 = blockIdx.y * 128;
    if (m0 >= cnt) return;
    int base = g_off[e];
    int n0 = blockIdx.x * 64;

    extern __shared__ __align__(16) char dsm[];
    int* toks = (int*)dsm;
    uint32_t sb = smem_u32(dsm);

    int tid = threadIdx.x, wid = tid >> 5, lane = tid & 31;
    int gid = lane >> 2, tig = lane & 3;
    int mb = (wid & 3) * 32;
    int nb = (wid >> 2) * 32;

    if (tid < 128) {
        int idx = m0 + tid;
        toks[tid] = (idx < cnt) ? g_slot_tok[base + idx] : -1;
    }
    __syncthreads();

    const __half* Wg = g_wg16 + (size_t)e * H_DIM * F_DIM + n0;
    const __half* Wu = g_wu16 + (size_t)e * H_DIM * F_DIM + n0;

    // staging: A 128r x 4 slots (512 slots, 2/thread); B each 32r x 8 slots (256, 1/thread)
    int a_row[2], a_j[2];
#pragma unroll
    for (int i = 0; i < 2; i++) {
        int i2 = tid + i * 256;
        a_row[i] = i2 >> 2;  a_j[i] = i2 & 3;
    }
    int b_row = tid >> 3, b_j = tid & 7;

    const int NCH = H_DIM / 32;  // 32
#define ISSUE_A(c, s)                                                                  \
    {                                                                                  \
        int k0 = (c) * 32;                                                             \
        uint32_t stg_i = sb + 512 + (s) * STG_A;                                       \
        _Pragma("unroll")                                                              \
        for (int i = 0; i < 2; i++) {                                                  \
            int tok = toks[a_row[i]];                                                  \
            const __half* src = g_x16 + (size_t)(tok < 0 ? 0 : tok) * H_DIM + k0 + a_j[i] * 8; \
            cp16(stg_i + a_row[i] * 80 + a_j[i] * 16, src, tok >= 0 ? 16u : 0u);       \
        }                                                                              \
        cp16(stg_i + 10240 + b_row * 144 + b_j * 16,                                   \
             Wg + (size_t)(k0 + b_row) * F_DIM + b_j * 8, 16u);                        \
        cp16(stg_i + 14848 + b_row * 144 + b_j * 16,                                   \
             Wu + (size_t)(k0 + b_row) * F_DIM + b_j * 8, 16u);                        \
        cp_commit();                                                                   \
    }

    ISSUE_A(0, 0);
    ISSUE_A(1, 1);

    float accG[2][4][4], accU[2][4][4];
#pragma unroll
    for (int mt = 0; mt < 2; mt++)
#pragma unroll
        for (int nt = 0; nt < 4; nt++)
#pragma unroll
            for (int i = 0; i < 4; i++) { accG[mt][nt][i] = 0.f; accU[mt][nt][i] = 0.f; }

    uint32_t aOff = (uint32_t)((mb + (lane & 15)) * 80 + (lane >> 4) * 16);
    uint32_t bOff = (uint32_t)((lane & 15) * 144 + (lane >> 4) * 16);

    for (int c = 0; c < NCH; c++) {
        if (c + 1 < NCH) asm volatile("cp.async.wait_group 1;" ::: "memory");
        else             asm volatile("cp.async.wait_group 0;" ::: "memory");
        __syncthreads();
        if (c + 2 < NCH) ISSUE_A(c + 2, (c + 2) % 3);
        uint32_t stg = sb + 512 + (c % 3) * STG_A;
#pragma unroll
        for (int ks = 0; ks < 2; ks++) {
            uint32_t af[2][4];
#pragma unroll
            for (int mt = 0; mt < 2; mt++)
                ldsm4(af[mt], stg + aOff + mt * 16 * 80 + ks * 32);
            uint32_t bg[2][4], bu[2][4];
#pragma unroll
            for (int pr = 0; pr < 2; pr++) {
                uint32_t co = (uint32_t)((nb + pr * 16) * 2 + ks * 16 * 144);
                ldsm4t(bg[pr], stg + 10240 + bOff + co);
                ldsm4t(bu[pr], stg + 14848 + bOff + co);
            }
#pragma unroll
            for (int pr = 0; pr < 2; pr++)
#pragma unroll
                for (int hn = 0; hn < 2; hn++) {
                    int nt = pr * 2 + hn;
#pragma unroll
                    for (int mt = 0; mt < 2; mt++) {
                        mma_f16(accG[mt][nt], af[mt], bg[pr] + hn * 2);
                        mma_f16(accU[mt][nt], af[mt], bu[pr] + hn * 2);
                    }
                }
        }
    }

    // epilogue: silu(gate)*up -> g_h16
#pragma unroll
    for (int mt = 0; mt < 2; mt++)
#pragma unroll
        for (int half = 0; half < 2; half++) {
            int r = m0 + mb + mt * 16 + gid + half * 8;
            if (r < cnt) {
                __half* hp = g_h16 + (size_t)(base + r) * F_DIM + n0 + nb + tig * 2;
#pragma unroll
                for (int nt = 0; nt < 4; nt++) {
                    float h0 = silu_mul(accG[mt][nt][half * 2 + 0], accU[mt][nt][half * 2 + 0]);
                    float h1 = silu_mul(accG[mt][nt][half * 2 + 1], accU[mt][nt][half * 2 + 1]);
                    *(__half2*)(hp + nt * 8) = __floats2half2_rn(h0, h1);
                }
            }
        }
#undef ISSUE_A
}

// ================= pass B: out += w * (H1 Wd), fp16 mma, 256 threads, 2 CTA/SM =======
// CTA 128M x 128N, BK=32, 8 warps (4m x 2n), warp tile 32x64. (R11 config, unchanged)
#define STG_B 18944
#define SMEM_B_BYTES (3 * STG_B)

__global__ void __launch_bounds__(256, 2)
gemmB_kernel(float* __restrict__ out) {
    int e = blockIdx.z;
    int cnt = g_count[e];
    int m0 = blockIdx.y * 128;
    if (m0 >= cnt) return;
    int base = g_off[e];
    int n0 = blockIdx.x * 128;

    extern __shared__ __align__(16) char dsm[];
    uint32_t sb = smem_u32(dsm);

    int tid = threadIdx.x, wid = tid >> 5, lane = tid & 31;
    int gid = lane >> 2, tig = lane & 3;
    int mb = (wid & 3) * 32;
    int nb = (wid >> 2) * 64;

    const __half* Wd = g_wd16 + (size_t)e * F_DIM * H_DIM + n0;

    int a_row[2], a_j[2], b_row[2], b_j[2];
#pragma unroll
    for (int i = 0; i < 2; i++) {
        int i2 = tid + i * 256;
        a_row[i] = i2 >> 2;  a_j[i] = i2 & 3;
        b_row[i] = i2 >> 4;  b_j[i] = i2 & 15;
    }

    const int NCH = F_DIM / 32;  // 128
#define ISSUE_B(c, s)                                                                  \
    {                                                                                  \
        int k0 = (c) * 32;                                                             \
        uint32_t stg_i = sb + (s) * STG_B;                                             \
        _Pragma("unroll")                                                              \
        for (int i = 0; i < 2; i++) {                                                  \
            int r = m0 + a_row[i];                                                     \
            int ok = (r < cnt);                                                        \
            const __half* src = g_h16 + (size_t)(base + (ok ? r : 0)) * F_DIM + k0 + a_j[i] * 8; \
            cp16(stg_i + a_row[i] * 80 + a_j[i] * 16, src, ok ? 16u : 0u);             \
            cp16(stg_i + 10240 + b_row[i] * 272 + b_j[i] * 16,                         \
                 Wd + (size_t)(k0 + b_row[i]) * H_DIM + b_j[i] * 8, 16u);              \
        }                                                                              \
        cp_commit();                                                                   \
    }

    ISSUE_B(0, 0);
    ISSUE_B(1, 1);

    float acc[2][8][4];
#pragma unroll
    for (int mt = 0; mt < 2; mt++)
#pragma unroll
        for (int nt = 0; nt < 8; nt++)
#pragma unroll
            for (int i = 0; i < 4; i++) acc[mt][nt][i] = 0.f;

    uint32_t aOff = (uint32_t)((mb + (lane & 15)) * 80 + (lane >> 4) * 16);
    uint32_t bOff = (uint32_t)((lane & 15) * 272 + (lane >> 4) * 16);

    for (int c = 0; c < NCH; c++) {
        if (c + 1 < NCH) asm volatile("cp.async.wait_group 1;" ::: "memory");
        else             asm volatile("cp.async.wait_group 0;" ::: "memory");
        __syncthreads();
        if (c + 2 < NCH) ISSUE_B(c + 2, (c + 2) % 3);
        uint32_t stg = sb + (c % 3) * STG_B;
#pragma unroll
        for (int ks = 0; ks < 2; ks++) {
            uint32_t af[2][4];
#pragma unroll
            for (int mt = 0; mt < 2; mt++)
                ldsm4(af[mt], stg + aOff + mt * 16 * 80 + ks * 32);
            uint32_t bf[4][4];
#pragma unroll
            for (int pr = 0; pr < 4; pr++) {
                uint32_t co = (uint32_t)((nb + pr * 16) * 2 + ks * 16 * 272);
                ldsm4t(bf[pr], stg + 10240 + bOff + co);
            }
#pragma unroll
            for (int pr = 0; pr < 4; pr++)
#pragma unroll
                for (int hn = 0; hn < 2; hn++) {
                    int nt = pr * 2 + hn;
#pragma unroll
                    for (int mt = 0; mt < 2; mt++)
                        mma_f16(acc[mt][nt], af[mt], bf[pr] + hn * 2);
                }
        }
    }

    // epilogue: weighted atomic combine
#pragma unroll
    for (int mt = 0; mt < 2; mt++)
#pragma unroll
        for (int half = 0; half < 2; half++) {
            int r = m0 + mb + mt * 16 + gid + half * 8;
            if (r < cnt) {
                int tok = g_slot_tok[base + r];
                float w = g_slot_w[base + r];
                float* op = out + (size_t)tok * H_DIM + n0 + nb + tig * 2;
#pragma unroll
                for (int nt = 0; nt < 8; nt++) {
                    atomicAdd(op + nt * 8 + 0, w * acc[mt][nt][half * 2 + 0]);
                    atomicAdd(op + nt * 8 + 1, w * acc[mt][nt][half * 2 + 1]);
                }
            }
        }
#undef ISSUE_B
}

// ---------------- launch (single stream) ----------------
extern "C" void kernel_launch(void* const* d_in, const int* in_sizes, int n_in,
                              void* d_out, int out_size) {
    const float* x  = (const float*)d_in[0];
    const float* gw = (const float*)d_in[1];
    const float* wg = (const float*)d_in[2];
    const float* wu = (const float*)d_in[3];
    const float* wd = (const float*)d_in[4];
    float* out = (float*)d_out;

    cudaFuncSetAttribute(gemmA_kernel, cudaFuncAttributeMaxDynamicSharedMemorySize, SMEM_A_BYTES);
    cudaFuncSetAttribute(gemmB_kernel, cudaFuncAttributeMaxDynamicSharedMemorySize, SMEM_B_BYTES);

    init_kernel<<<512, 256>>>(out, out_size);

    __half* dg; __half* du; __half* dd;
    cudaGetSymbolAddress((void**)&dg, g_wg16);
    cudaGetSymbolAddress((void**)&du, g_wu16);
    cudaGetSymbolAddress((void**)&dd, g_wd16);
    const int NW = E_NUM * H_DIM * F_DIM;
    dim3 gC(NW / 1024, 3);
    conv3_kernel<<<gC, 256>>>(wg, wu, wd, dg, du, dd, NW);

    router_kernel<<<T_TOK / 8, 256>>>(x, gw);   // also writes g_x16
    scatter_kernel<<<T_TOK / 256, 256>>>();     // computes + publishes g_off
    reduce_kernel<<<1, 256>>>(out, out_size);

    dim3 gA(F_DIM / 64, N_SLOTS / 128, E_NUM);
    gemmA_kernel<<<gA, 256, SMEM_A_BYTES>>>();

    dim3 gB(H_DIM / 128, N_SLOTS / 128, E_NUM);
    gemmB_kernel<<<gB, 256, SMEM_B_BYTES>>>(out);
}

// round 13
// speedup vs baseline: 1.1947x; 1.0040x over previous
#include <cuda_runtime.h>
#include <cuda_fp16.h>
#include <math.h>
#include <stdint.h>

#define T_TOK 8192
#define H_DIM 1024
#define F_DIM 4096
#define E_NUM 8
#define N_SLOTS (T_TOK * 2)

// ---------------- scratch (device globals; no runtime allocation) ----------------
__device__ float g_probs[T_TOK * E_NUM];
__device__ float g_lse2[T_TOK];
__device__ int   g_tok_e[T_TOK * 2];
__device__ float g_tok_w[T_TOK * 2];
__device__ int   g_count[E_NUM];
__device__ int   g_off[E_NUM + 1];
__device__ int   g_cursor[E_NUM];
__device__ int   g_slot_tok[N_SLOTS];
__device__ float g_slot_w[N_SLOTS];

__device__ __half g_x16[(size_t)T_TOK * H_DIM];
__device__ __half g_wg16[(size_t)E_NUM * H_DIM * F_DIM];
__device__ __half g_wu16[(size_t)E_NUM * H_DIM * F_DIM];
__device__ __half g_wd16[(size_t)E_NUM * F_DIM * H_DIM];
__device__ __half g_h16[(size_t)N_SLOTS * F_DIM];   // 128 MB fp16 intermediate

// ---------------- PTX helpers ----------------
__device__ __forceinline__ uint32_t smem_u32(const void* p) {
    uint32_t a;
    asm("{ .reg .u64 t; cvta.to.shared.u64 t, %1; cvt.u32.u64 %0, t; }" : "=r"(a) : "l"(p));
    return a;
}
__device__ __forceinline__ void cp16(uint32_t dst, const void* src, uint32_t sz) {
    asm volatile("cp.async.cg.shared.global [%0], [%1], 16, %2;"
                 :: "r"(dst), "l"(__cvta_generic_to_global(src)), "r"(sz) : "memory");
}
__device__ __forceinline__ void cp_commit() {
    asm volatile("cp.async.commit_group;" ::: "memory");
}
__device__ __forceinline__ void ldsm4(uint32_t* r, uint32_t a) {
    asm volatile("ldmatrix.sync.aligned.m8n8.x4.shared.b16 {%0,%1,%2,%3}, [%4];"
                 : "=r"(r[0]), "=r"(r[1]), "=r"(r[2]), "=r"(r[3]) : "r"(a));
}
__device__ __forceinline__ void ldsm4t(uint32_t* r, uint32_t a) {
    asm volatile("ldmatrix.sync.aligned.m8n8.x4.trans.shared.b16 {%0,%1,%2,%3}, [%4];"
                 : "=r"(r[0]), "=r"(r[1]), "=r"(r[2]), "=r"(r[3]) : "r"(a));
}
__device__ __forceinline__ void mma_f16(float* c, const uint32_t* a, const uint32_t* b) {
    asm volatile("mma.sync.aligned.m16n8k16.row.col.f32.f16.f16.f32 "
                 "{%0,%1,%2,%3}, {%4,%5,%6,%7}, {%8,%9}, {%0,%1,%2,%3};"
                 : "+f"(c[0]), "+f"(c[1]), "+f"(c[2]), "+f"(c[3])
                 : "r"(a[0]), "r"(a[1]), "r"(a[2]), "r"(a[3]), "r"(b[0]), "r"(b[1]));
}
__device__ __forceinline__ float silu_mul(float g, float u) {
    return g / (1.f + __expf(-g)) * u;
}

// ---------------- init ----------------
__global__ void init_kernel(float* out, int n) {
    int tid = blockIdx.x * blockDim.x + threadIdx.x;
    if (tid < E_NUM) { g_count[tid] = 0; g_cursor[tid] = 0; }
    for (int i = tid; i < n; i += gridDim.x * blockDim.x) out[i] = 0.f;
}

// ---------------- fp32 -> fp16 conversion (all 3 weight tensors, one launch) ----------------
__global__ void conv3_kernel(const float* __restrict__ wg, const float* __restrict__ wu,
                             const float* __restrict__ wd,
                             __half* __restrict__ dg, __half* __restrict__ du,
                             __half* __restrict__ dd, int n) {
    const float* s = (blockIdx.y == 0) ? wg : (blockIdx.y == 1) ? wu : wd;
    __half* d = (blockIdx.y == 0) ? dg : (blockIdx.y == 1) ? du : dd;
    int i = (blockIdx.x * 256 + threadIdx.x) * 4;
    if (i >= n) return;
    float4 v = *(const float4*)(s + i);
    union { __half2 h[2]; uint2 u; } pk;
    pk.h[0] = __floats2half2_rn(v.x, v.y);
    pk.h[1] = __floats2half2_rn(v.z, v.w);
    *(uint2*)(d + i) = pk.u;
}

// ---------------- router: one warp per token (also emits x as fp16) ----------------
__global__ void router_kernel(const float* __restrict__ x, const float* __restrict__ gw) {
    __shared__ float sgw[H_DIM * E_NUM];
    for (int i = threadIdx.x; i < H_DIM * E_NUM; i += blockDim.x) sgw[i] = gw[i];
    __syncthreads();

    int warp = threadIdx.x >> 5;
    int lane = threadIdx.x & 31;
    int t = blockIdx.x * (blockDim.x >> 5) + warp;
    if (t >= T_TOK) return;

    const float* xr = x + (size_t)t * H_DIM;
    float acc[E_NUM];
#pragma unroll
    for (int e = 0; e < E_NUM; e++) acc[e] = 0.f;
    for (int h = lane; h < H_DIM; h += 32) {
        float xv = xr[h];
#pragma unroll
        for (int e = 0; e < E_NUM; e++) acc[e] += xv * sgw[h * E_NUM + e];
    }

    {
        __half* dx = g_x16 + (size_t)t * H_DIM;
#pragma unroll
        for (int k = 0; k < H_DIM / 4 / 32; k++) {
            int idx = (lane + k * 32) * 4;
            float4 v = *(const float4*)(xr + idx);
            union { __half2 h[2]; uint2 u; } pk;
            pk.h[0] = __floats2half2_rn(v.x, v.y);
            pk.h[1] = __floats2half2_rn(v.z, v.w);
            *(uint2*)(dx + idx) = pk.u;
        }
    }

#pragma unroll
    for (int off = 16; off; off >>= 1)
#pragma unroll
        for (int e = 0; e < E_NUM; e++) acc[e] += __shfl_xor_sync(0xffffffffu, acc[e], off);

    if (lane == 0) {
        float m = acc[0];
#pragma unroll
        for (int e = 1; e < E_NUM; e++) m = fmaxf(m, acc[e]);
        float p[E_NUM], s = 0.f;
#pragma unroll
        for (int e = 0; e < E_NUM; e++) { p[e] = expf(acc[e] - m); s += p[e]; }
        float lse = m + logf(s);
        g_lse2[t] = lse * lse;
        float inv = 1.f / s;
#pragma unroll
        for (int e = 0; e < E_NUM; e++) { p[e] *= inv; g_probs[t * E_NUM + e] = p[e]; }
        int i1 = 0;
#pragma unroll
        for (int e = 1; e < E_NUM; e++) if (p[e] > p[i1]) i1 = e;
        int i2 = (i1 == 0) ? 1 : 0;
#pragma unroll
        for (int e = 0; e < E_NUM; e++) if (e != i1 && p[e] > p[i2]) i2 = e;
        float w1 = p[i1], w2 = p[i2];
        float ws = 1.f / (w1 + w2);
        g_tok_e[2 * t + 0] = i1;  g_tok_w[2 * t + 0] = w1 * ws;
        g_tok_e[2 * t + 1] = i2;  g_tok_w[2 * t + 1] = w2 * ws;
        atomicAdd(&g_count[i1], 1);
        atomicAdd(&g_count[i2], 1);
    }
}

// ---------------- scatter (computes offsets locally; block 0 publishes g_off) ----------------
__global__ void scatter_kernel() {
    int off[E_NUM + 1];
    off[0] = 0;
#pragma unroll
    for (int e = 0; e < E_NUM; e++) off[e + 1] = off[e] + g_count[e];

    int t = blockIdx.x * blockDim.x + threadIdx.x;
    if (blockIdx.x == 0 && threadIdx.x == 0) {
#pragma unroll
        for (int e = 0; e <= E_NUM; e++) g_off[e] = off[e];
    }
    if (t >= T_TOK) return;
#pragma unroll
    for (int k = 0; k < 2; k++) {
        int e = g_tok_e[2 * t + k];
        int pos = off[e] + atomicAdd(&g_cursor[e], 1);
        g_slot_tok[pos] = t;
        g_slot_w[pos] = g_tok_w[2 * t + k];
    }
}

__global__ void reduce_kernel(float* out, int out_size) {
    __shared__ float sp[256 * E_NUM];
    __shared__ float sl[256];
    int tid = threadIdx.x;
    float lp[E_NUM];
#pragma unroll
    for (int e = 0; e < E_NUM; e++) lp[e] = 0.f;
    float ll = 0.f;
    for (int t = tid; t < T_TOK; t += 256) {
#pragma unroll
        for (int e = 0; e < E_NUM; e++) lp[e] += g_probs[t * E_NUM + e];
        ll += g_lse2[t];
    }
#pragma unroll
    for (int e = 0; e < E_NUM; e++) sp[tid * E_NUM + e] = lp[e];
    sl[tid] = ll;
    __syncthreads();
    for (int s = 128; s; s >>= 1) {
        if (tid < s) {
#pragma unroll
            for (int e = 0; e < E_NUM; e++) sp[tid * E_NUM + e] += sp[(tid + s) * E_NUM + e];
            sl[tid] += sl[tid + s];
        }
        __syncthreads();
    }
    if (tid == 0) {
        float bal = 0.f;
        for (int e = 0; e < E_NUM; e++) {
            float frac = (float)g_count[e] / (float)(T_TOK * 2);
            float meanp = sp[e] / (float)T_TOK;
            bal += frac * meanp;
        }
        out[out_size - 2] = bal * (float)E_NUM;
        out[out_size - 1] = sl[0] / (float)T_TOK;
    }
}

// ================= pass A: h = silu(X Wg)*(X Wu), fp16 mma, 256 threads, 2 CTA/SM =====
// CTA 128M x 64N(gate)+64N(up), BK=32, 8 warps (4m x 2n), warp tile 32x32 per matrix.
// SMEM strides (bytes): A rows 80, B rows 144. 3-stage cp.async, 1 sync/iter.
#define STG_A 19456
#define SMEM_A_BYTES (512 + 3 * STG_A)

__global__ void __launch_bounds__(256, 2)
gemmA_kernel() {
    int e = blockIdx.z;
    int cnt = g_count[e];
    int m0 = blockIdx.y * 128;
    if (m0 >= cnt) return;
    int base = g_off[e];
    int n0 = blockIdx.x * 64;

    extern __shared__ __align__(16) char dsm[];
    int* toks = (int*)dsm;
    uint32_t sb = smem_u32(dsm);

    int tid = threadIdx.x, wid = tid >> 5, lane = tid & 31;
    int gid = lane >> 2, tig = lane & 3;
    int mb = (wid & 3) * 32;
    int nb = (wid >> 2) * 32;

    if (tid < 128) {
        int idx = m0 + tid;
        toks[tid] = (idx < cnt) ? g_slot_tok[base + idx] : -1;
    }
    __syncthreads();

    const __half* Wg = g_wg16 + (size_t)e * H_DIM * F_DIM + n0;
    const __half* Wu = g_wu16 + (size_t)e * H_DIM * F_DIM + n0;

    int a_row[2], a_j[2];
#pragma unroll
    for (int i = 0; i < 2; i++) {
        int i2 = tid + i * 256;
        a_row[i] = i2 >> 2;  a_j[i] = i2 & 3;
    }
    int b_row = tid >> 3, b_j = tid & 7;

    const int NCH = H_DIM / 32;  // 32
#define ISSUE_A(c, s)                                                                  \
    {                                                                                  \
        int k0 = (c) * 32;                                                             \
        uint32_t stg_i = sb + 512 + (s) * STG_A;                                       \
        _Pragma("unroll")                                                              \
        for (int i = 0; i < 2; i++) {                                                  \
            int tok = toks[a_row[i]];                                                  \
            const __half* src = g_x16 + (size_t)(tok < 0 ? 0 : tok) * H_DIM + k0 + a_j[i] * 8; \
            cp16(stg_i + a_row[i] * 80 + a_j[i] * 16, src, tok >= 0 ? 16u : 0u);       \
        }                                                                              \
        cp16(stg_i + 10240 + b_row * 144 + b_j * 16,                                   \
             Wg + (size_t)(k0 + b_row) * F_DIM + b_j * 8, 16u);                        \
        cp16(stg_i + 14848 + b_row * 144 + b_j * 16,                                   \
             Wu + (size_t)(k0 + b_row) * F_DIM + b_j * 8, 16u);                        \
        cp_commit();                                                                   \
    }

    ISSUE_A(0, 0);
    ISSUE_A(1, 1);

    float accG[2][4][4], accU[2][4][4];
#pragma unroll
    for (int mt = 0; mt < 2; mt++)
#pragma unroll
        for (int nt = 0; nt < 4; nt++)
#pragma unroll
            for (int i = 0; i < 4; i++) { accG[mt][nt][i] = 0.f; accU[mt][nt][i] = 0.f; }

    uint32_t aOff = (uint32_t)((mb + (lane & 15)) * 80 + (lane >> 4) * 16);
    uint32_t bOff = (uint32_t)((lane & 15) * 144 + (lane >> 4) * 16);

    for (int c = 0; c < NCH; c++) {
        if (c + 1 < NCH) asm volatile("cp.async.wait_group 1;" ::: "memory");
        else             asm volatile("cp.async.wait_group 0;" ::: "memory");
        __syncthreads();
        if (c + 2 < NCH) ISSUE_A(c + 2, (c + 2) % 3);
        uint32_t stg = sb + 512 + (c % 3) * STG_A;
#pragma unroll
        for (int ks = 0; ks < 2; ks++) {
            uint32_t af[2][4];
#pragma unroll
            for (int mt = 0; mt < 2; mt++)
                ldsm4(af[mt], stg + aOff + mt * 16 * 80 + ks * 32);
            uint32_t bg[2][4], bu[2][4];
#pragma unroll
            for (int pr = 0; pr < 2; pr++) {
                uint32_t co = (uint32_t)((nb + pr * 16) * 2 + ks * 16 * 144);
                ldsm4t(bg[pr], stg + 10240 + bOff + co);
                ldsm4t(bu[pr], stg + 14848 + bOff + co);
            }
#pragma unroll
            for (int pr = 0; pr < 2; pr++)
#pragma unroll
                for (int hn = 0; hn < 2; hn++) {
                    int nt = pr * 2 + hn;
#pragma unroll
                    for (int mt = 0; mt < 2; mt++) {
                        mma_f16(accG[mt][nt], af[mt], bg[pr] + hn * 2);
                        mma_f16(accU[mt][nt], af[mt], bu[pr] + hn * 2);
                    }
                }
        }
    }

    // epilogue: silu(gate)*up -> g_h16
#pragma unroll
    for (int mt = 0; mt < 2; mt++)
#pragma unroll
        for (int half = 0; half < 2; half++) {
            int r = m0 + mb + mt * 16 + gid + half * 8;
            if (r < cnt) {
                __half* hp = g_h16 + (size_t)(base + r) * F_DIM + n0 + nb + tig * 2;
#pragma unroll
                for (int nt = 0; nt < 4; nt++) {
                    float h0 = silu_mul(accG[mt][nt][half * 2 + 0], accU[mt][nt][half * 2 + 0]);
                    float h1 = silu_mul(accG[mt][nt][half * 2 + 1], accU[mt][nt][half * 2 + 1]);
                    *(__half2*)(hp + nt * 8) = __floats2half2_rn(h0, h1);
                }
            }
        }
#undef ISSUE_A
}

// ================= pass B: out += w * (H1 Wd), fp16 mma, 256 threads, 2 CTA/SM =======
// CTA 128M x 128N, BK=32, 8 warps (4m x 2n), warp tile 32x64. (unchanged)
#define STG_B 18944
#define SMEM_B_BYTES (3 * STG_B)

__global__ void __launch_bounds__(256, 2)
gemmB_kernel(float* __restrict__ out) {
    int e = blockIdx.z;
    int cnt = g_count[e];
    int m0 = blockIdx.y * 128;
    if (m0 >= cnt) return;
    int base = g_off[e];
    int n0 = blockIdx.x * 128;

    extern __shared__ __align__(16) char dsm[];
    uint32_t sb = smem_u32(dsm);

    int tid = threadIdx.x, wid = tid >> 5, lane = tid & 31;
    int gid = lane >> 2, tig = lane & 3;
    int mb = (wid & 3) * 32;
    int nb = (wid >> 2) * 64;

    const __half* Wd = g_wd16 + (size_t)e * F_DIM * H_DIM + n0;

    int a_row[2], a_j[2], b_row[2], b_j[2];
#pragma unroll
    for (int i = 0; i < 2; i++) {
        int i2 = tid + i * 256;
        a_row[i] = i2 >> 2;  a_j[i] = i2 & 3;
        b_row[i] = i2 >> 4;  b_j[i] = i2 & 15;
    }

    const int NCH = F_DIM / 32;  // 128
#define ISSUE_B(c, s)                                                                  \
    {                                                                                  \
        int k0 = (c) * 32;                                                             \
        uint32_t stg_i = sb + (s) * STG_B;                                             \
        _Pragma("unroll")                                                              \
        for (int i = 0; i < 2; i++) {                                                  \
            int r = m0 + a_row[i];                                                     \
            int ok = (r < cnt);                                                        \
            const __half* src = g_h16 + (size_t)(base + (ok ? r : 0)) * F_DIM + k0 + a_j[i] * 8; \
            cp16(stg_i + a_row[i] * 80 + a_j[i] * 16, src, ok ? 16u : 0u);             \
            cp16(stg_i + 10240 + b_row[i] * 272 + b_j[i] * 16,                         \
                 Wd + (size_t)(k0 + b_row[i]) * H_DIM + b_j[i] * 8, 16u);              \
        }                                                                              \
        cp_commit();                                                                   \
    }

    ISSUE_B(0, 0);
    ISSUE_B(1, 1);

    float acc[2][8][4];
#pragma unroll
    for (int mt = 0; mt < 2; mt++)
#pragma unroll
        for (int nt = 0; nt < 8; nt++)
#pragma unroll
            for (int i = 0; i < 4; i++) acc[mt][nt][i] = 0.f;

    uint32_t aOff = (uint32_t)((mb + (lane & 15)) * 80 + (lane >> 4) * 16);
    uint32_t bOff = (uint32_t)((lane & 15) * 272 + (lane >> 4) * 16);

    for (int c = 0; c < NCH; c++) {
        if (c + 1 < NCH) asm volatile("cp.async.wait_group 1;" ::: "memory");
        else             asm volatile("cp.async.wait_group 0;" ::: "memory");
        __syncthreads();
        if (c + 2 < NCH) ISSUE_B(c + 2, (c + 2) % 3);
        uint32_t stg = sb + (c % 3) * STG_B;
#pragma unroll
        for (int ks = 0; ks < 2; ks++) {
            uint32_t af[2][4];
#pragma unroll
            for (int mt = 0; mt < 2; mt++)
                ldsm4(af[mt], stg + aOff + mt * 16 * 80 + ks * 32);
            uint32_t bf[4][4];
#pragma unroll
            for (int pr = 0; pr < 4; pr++) {
                uint32_t co = (uint32_t)((nb + pr * 16) * 2 + ks * 16 * 272);
                ldsm4t(bf[pr], stg + 10240 + bOff + co);
            }
#pragma unroll
            for (int pr = 0; pr < 4; pr++)
#pragma unroll
                for (int hn = 0; hn < 2; hn++) {
                    int nt = pr * 2 + hn;
#pragma unroll
                    for (int mt = 0; mt < 2; mt++)
                        mma_f16(acc[mt][nt], af[mt], bf[pr] + hn * 2);
                }
        }
    }

    // epilogue: weighted atomic combine
#pragma unroll
    for (int mt = 0; mt < 2; mt++)
#pragma unroll
        for (int half = 0; half < 2; half++) {
            int r = m0 + mb + mt * 16 + gid + half * 8;
            if (r < cnt) {
                int tok = g_slot_tok[base + r];
                float w = g_slot_w[base + r];
                float* op = out + (size_t)tok * H_DIM + n0 + nb + tig * 2;
#pragma unroll
                for (int nt = 0; nt < 8; nt++) {
                    atomicAdd(op + nt * 8 + 0, w * acc[mt][nt][half * 2 + 0]);
                    atomicAdd(op + nt * 8 + 1, w * acc[mt][nt][half * 2 + 1]);
                }
            }
        }
#undef ISSUE_B
}

// ---------------- launch: conv3 (main) ‖ init+router chain (side), join before GEMMs ----
extern "C" void kernel_launch(void* const* d_in, const int* in_sizes, int n_in,
                              void* d_out, int out_size) {
    const float* x  = (const float*)d_in[0];
    const float* gw = (const float*)d_in[1];
    const float* wg = (const float*)d_in[2];
    const float* wu = (const float*)d_in[3];
    const float* wd = (const float*)d_in[4];
    float* out = (float*)d_out;

    static cudaStream_t s1 = nullptr;
    static cudaEvent_t e0 = nullptr, e1 = nullptr;
    if (s1 == nullptr) {
        cudaStreamCreateWithFlags(&s1, cudaStreamNonBlocking);
        cudaEventCreateWithFlags(&e0, cudaEventDisableTiming);
        cudaEventCreateWithFlags(&e1, cudaEventDisableTiming);
        cudaFuncSetAttribute(gemmA_kernel, cudaFuncAttributeMaxDynamicSharedMemorySize, SMEM_A_BYTES);
        cudaFuncSetAttribute(gemmB_kernel, cudaFuncAttributeMaxDynamicSharedMemorySize, SMEM_B_BYTES);
    }

    __half* dg; __half* du; __half* dd;
    cudaGetSymbolAddress((void**)&dg, g_wg16);
    cudaGetSymbolAddress((void**)&du, g_wu16);
    cudaGetSymbolAddress((void**)&dd, g_wd16);
    const int NW = E_NUM * H_DIM * F_DIM;

    // fork
    cudaEventRecord(e0, 0);
    cudaStreamWaitEvent(s1, e0, 0);

    // side: init -> router -> scatter -> reduce (no GEMM running concurrently)
    init_kernel<<<512, 256, 0, s1>>>(out, out_size);
    router_kernel<<<T_TOK / 8, 256, 0, s1>>>(x, gw);   // also writes g_x16
    scatter_kernel<<<T_TOK / 256, 256, 0, s1>>>();     // computes + publishes g_off
    reduce_kernel<<<1, 256, 0, s1>>>(out, out_size);
    cudaEventRecord(e1, s1);

    // main: weight conversion
    dim3 gC(NW / 1024, 3);
    conv3_kernel<<<gC, 256>>>(wg, wu, wd, dg, du, dd, NW);

    // join, then GEMMs
    cudaStreamWaitEvent(0, e1, 0);
    dim3 gA(F_DIM / 64, N_SLOTS / 128, E_NUM);
    gemmA_kernel<<<gA, 256, SMEM_A_BYTES>>>();

    dim3 gB(H_DIM / 128, N_SLOTS / 128, E_NUM);
    gemmB_kernel<<<gB, 256, SMEM_B_BYTES>>>(out);
}

// round 15
// speedup vs baseline: 1.2284x; 1.0282x over previous
#include <cuda_runtime.h>
#include <cuda_fp16.h>
#include <math.h>
#include <stdint.h>

#define T_TOK 8192
#define H_DIM 1024
#define F_DIM 4096
#define E_NUM 8
#define N_SLOTS (T_TOK * 2)
#define MAX_BLK 144

// ---------------- scratch (device globals; no runtime allocation) ----------------
__device__ float g_probs[T_TOK * E_NUM];
__device__ float g_lse2[T_TOK];
__device__ int   g_tok_e[T_TOK * 2];
__device__ float g_tok_w[T_TOK * 2];
__device__ int   g_count[E_NUM];
__device__ int   g_off[E_NUM + 1];
__device__ int   g_cursor[E_NUM];
__device__ int   g_slot_tok[N_SLOTS];
__device__ float g_slot_w[N_SLOTS];

__device__ int   g_nblk;
__device__ int   g_blk_e[MAX_BLK];
__device__ int   g_blk_m[MAX_BLK];

__device__ __half g_x16[(size_t)T_TOK * H_DIM];
__device__ __half g_wg16[(size_t)E_NUM * H_DIM * F_DIM];
__device__ __half g_wu16[(size_t)E_NUM * H_DIM * F_DIM];
__device__ __half g_wd16[(size_t)E_NUM * F_DIM * H_DIM];
__device__ __half g_h16[(size_t)N_SLOTS * F_DIM];   // 128 MB fp16 intermediate

// ---------------- PTX helpers ----------------
__device__ __forceinline__ uint32_t smem_u32(const void* p) {
    uint32_t a;
    asm("{ .reg .u64 t; cvta.to.shared.u64 t, %1; cvt.u32.u64 %0, t; }" : "=r"(a) : "l"(p));
    return a;
}
__device__ __forceinline__ void cp16(uint32_t dst, const void* src, uint32_t sz) {
    asm volatile("cp.async.cg.shared.global [%0], [%1], 16, %2;"
                 :: "r"(dst), "l"(__cvta_generic_to_global(src)), "r"(sz) : "memory");
}
__device__ __forceinline__ void cp_commit() {
    asm volatile("cp.async.commit_group;" ::: "memory");
}
__device__ __forceinline__ void ldsm4(uint32_t* r, uint32_t a) {
    asm volatile("ldmatrix.sync.aligned.m8n8.x4.shared.b16 {%0,%1,%2,%3}, [%4];"
                 : "=r"(r[0]), "=r"(r[1]), "=r"(r[2]), "=r"(r[3]) : "r"(a));
}
__device__ __forceinline__ void ldsm4t(uint32_t* r, uint32_t a) {
    asm volatile("ldmatrix.sync.aligned.m8n8.x4.trans.shared.b16 {%0,%1,%2,%3}, [%4];"
                 : "=r"(r[0]), "=r"(r[1]), "=r"(r[2]), "=r"(r[3]) : "r"(a));
}
__device__ __forceinline__ void mma_f16(float* c, const uint32_t* a, const uint32_t* b) {
    asm volatile("mma.sync.aligned.m16n8k16.row.col.f32.f16.f16.f32 "
                 "{%0,%1,%2,%3}, {%4,%5,%6,%7}, {%8,%9}, {%0,%1,%2,%3};"
                 : "+f"(c[0]), "+f"(c[1]), "+f"(c[2]), "+f"(c[3])
                 : "r"(a[0]), "r"(a[1]), "r"(a[2]), "r"(a[3]), "r"(b[0]), "r"(b[1]));
}
__device__ __forceinline__ float silu_mul(float g, float u) {
    return g / (1.f + __expf(-g)) * u;
}

// ---------------- init ----------------
__global__ void init_kernel(float* out, int n) {
    int tid = blockIdx.x * blockDim.x + threadIdx.x;
    if (tid < E_NUM) { g_count[tid] = 0; g_cursor[tid] = 0; }
    for (int i = tid; i < n; i += gridDim.x * blockDim.x) out[i] = 0.f;
}

// ---------------- fp32 -> fp16 conversion (all 3 weight tensors, one launch) ----------------
__global__ void conv3_kernel(const float* __restrict__ wg, const float* __restrict__ wu,
                             const float* __restrict__ wd,
                             __half* __restrict__ dg, __half* __restrict__ du,
                             __half* __restrict__ dd, int n) {
    const float* s = (blockIdx.y == 0) ? wg : (blockIdx.y == 1) ? wu : wd;
    __half* d = (blockIdx.y == 0) ? dg : (blockIdx.y == 1) ? du : dd;
    int i = (blockIdx.x * 256 + threadIdx.x) * 4;
    if (i >= n) return;
    float4 v = *(const float4*)(s + i);
    union { __half2 h[2]; uint2 u; } pk;
    pk.h[0] = __floats2half2_rn(v.x, v.y);
    pk.h[1] = __floats2half2_rn(v.z, v.w);
    *(uint2*)(d + i) = pk.u;
}

// ---------------- router: one warp per token (also emits x as fp16) ----------------
__global__ void router_kernel(const float* __restrict__ x, const float* __restrict__ gw) {
    __shared__ float sgw[H_DIM * E_NUM];
    for (int i = threadIdx.x; i < H_DIM * E_NUM; i += blockDim.x) sgw[i] = gw[i];
    __syncthreads();

    int warp = threadIdx.x >> 5;
    int lane = threadIdx.x & 31;
    int t = blockIdx.x * (blockDim.x >> 5) + warp;
    if (t >= T_TOK) return;

    const float* xr = x + (size_t)t * H_DIM;
    float acc[E_NUM];
#pragma unroll
    for (int e = 0; e < E_NUM; e++) acc[e] = 0.f;
    for (int h = lane; h < H_DIM; h += 32) {
        float xv = xr[h];
#pragma unroll
        for (int e = 0; e < E_NUM; e++) acc[e] += xv * sgw[h * E_NUM + e];
    }

    {
        __half* dx = g_x16 + (size_t)t * H_DIM;
#pragma unroll
        for (int k = 0; k < H_DIM / 4 / 32; k++) {
            int idx = (lane + k * 32) * 4;
            float4 v = *(const float4*)(xr + idx);
            union { __half2 h[2]; uint2 u; } pk;
            pk.h[0] = __floats2half2_rn(v.x, v.y);
            pk.h[1] = __floats2half2_rn(v.z, v.w);
            *(uint2*)(dx + idx) = pk.u;
        }
    }

#pragma unroll
    for (int off = 16; off; off >>= 1)
#pragma unroll
        for (int e = 0; e < E_NUM; e++) acc[e] += __shfl_xor_sync(0xffffffffu, acc[e], off);

    if (lane == 0) {
        float m = acc[0];
#pragma unroll
        for (int e = 1; e < E_NUM; e++) m = fmaxf(m, acc[e]);
        float p[E_NUM], s = 0.f;
#pragma unroll
        for (int e = 0; e < E_NUM; e++) { p[e] = expf(acc[e] - m); s += p[e]; }
        float lse = m + logf(s);
        g_lse2[t] = lse * lse;
        float inv = 1.f / s;
#pragma unroll
        for (int e = 0; e < E_NUM; e++) { p[e] *= inv; g_probs[t * E_NUM + e] = p[e]; }
        int i1 = 0;
#pragma unroll
        for (int e = 1; e < E_NUM; e++) if (p[e] > p[i1]) i1 = e;
        int i2 = (i1 == 0) ? 1 : 0;
#pragma unroll
        for (int e = 0; e < E_NUM; e++) if (e != i1 && p[e] > p[i2]) i2 = e;
        float w1 = p[i1], w2 = p[i2];
        float ws = 1.f / (w1 + w2);
        g_tok_e[2 * t + 0] = i1;  g_tok_w[2 * t + 0] = w1 * ws;
        g_tok_e[2 * t + 1] = i2;  g_tok_w[2 * t + 1] = w2 * ws;
        atomicAdd(&g_count[i1], 1);
        atomicAdd(&g_count[i2], 1);
    }
}

// ---------------- scatter (publishes g_off + flat M-block table) ----------------
__global__ void scatter_kernel() {
    int off[E_NUM + 1];
    off[0] = 0;
#pragma unroll
    for (int e = 0; e < E_NUM; e++) off[e + 1] = off[e] + g_count[e];

    int t = blockIdx.x * blockDim.x + threadIdx.x;
    if (blockIdx.x == 0 && threadIdx.x == 0) {
#pragma unroll
        for (int e = 0; e <= E_NUM; e++) g_off[e] = off[e];
        int nb = 0;
        for (int e = 0; e < E_NUM; e++) {
            int cnt = off[e + 1] - off[e];
            for (int m0 = 0; m0 < cnt; m0 += 128) {
                g_blk_e[nb] = e;
                g_blk_m[nb] = m0;
                nb++;
            }
        }
        g_nblk = nb;
    }
    if (t >= T_TOK) return;
#pragma unroll
    for (int k = 0; k < 2; k++) {
        int e = g_tok_e[2 * t + k];
        int pos = off[e] + atomicAdd(&g_cursor[e], 1);
        g_slot_tok[pos] = t;
        g_slot_w[pos] = g_tok_w[2 * t + k];
    }
}

__global__ void reduce_kernel(float* out, int out_size) {
    __shared__ float sp[256 * E_NUM];
    __shared__ float sl[256];
    int tid = threadIdx.x;
    float lp[E_NUM];
#pragma unroll
    for (int e = 0; e < E_NUM; e++) lp[e] = 0.f;
    float ll = 0.f;
    for (int t = tid; t < T_TOK; t += 256) {
#pragma unroll
        for (int e = 0; e < E_NUM; e++) lp[e] += g_probs[t * E_NUM + e];
        ll += g_lse2[t];
    }
#pragma unroll
    for (int e = 0; e < E_NUM; e++) sp[tid * E_NUM + e] = lp[e];
    sl[tid] = ll;
    __syncthreads();
    for (int s = 128; s; s >>= 1) {
        if (tid < s) {
#pragma unroll
            for (int e = 0; e < E_NUM; e++) sp[tid * E_NUM + e] += sp[(tid + s) * E_NUM + e];
            sl[tid] += sl[tid + s];
        }
        __syncthreads();
    }
    if (tid == 0) {
        float bal = 0.f;
        for (int e = 0; e < E_NUM; e++) {
            float frac = (float)g_count[e] / (float)(T_TOK * 2);
            float meanp = sp[e] / (float)T_TOK;
            bal += frac * meanp;
        }
        out[out_size - 2] = bal * (float)E_NUM;
        out[out_size - 1] = sl[0] / (float)T_TOK;
    }
}

// ================= pass A: h = silu(X Wg)*(X Wu), fp16 mma, 256 threads, 2 CTA/SM =====
// CTA 128M x 64N(gate)+64N(up), BK=32, 8 warps (4m x 2n), warp tile 32x32 per matrix.
// M-block from flat table (no null-CTA storm). SMEM: A rows 80B, B rows 144B.
#define STG_A 19456
#define SMEM_A_BYTES (512 + 3 * STG_A)

__global__ void __launch_bounds__(256, 2)
gemmA_kernel() {
    int blk = blockIdx.y;
    if (blk >= g_nblk) return;
    int e = g_blk_e[blk];
    int m0 = g_blk_m[blk];
    int cnt = g_count[e];
    int base = g_off[e];
    int n0 = blockIdx.x * 64;

    extern __shared__ __align__(16) char dsm[];
    int* toks = (int*)dsm;
    uint32_t sb = smem_u32(dsm);

    int tid = threadIdx.x, wid = tid >> 5, lane = tid & 31;
    int gid = lane >> 2, tig = lane & 3;
    int mb = (wid & 3) * 32;
    int nb = (wid >> 2) * 32;

    if (tid < 128) {
        int idx = m0 + tid;
        toks[tid] = (idx < cnt) ? g_slot_tok[base + idx] : -1;
    }
    __syncthreads();

    const __half* Wg = g_wg16 + (size_t)e * H_DIM * F_DIM + n0;
    const __half* Wu = g_wu16 + (size_t)e * H_DIM * F_DIM + n0;

    int a_row[2], a_j[2];
#pragma unroll
    for (int i = 0; i < 2; i++) {
        int i2 = tid + i * 256;
        a_row[i] = i2 >> 2;  a_j[i] = i2 & 3;
    }
    int b_row = tid >> 3, b_j = tid & 7;

    const int NCH = H_DIM / 32;  // 32
#define ISSUE_A(c, s)                                                                  \
    {                                                                                  \
        int k0 = (c) * 32;                                                             \
        uint32_t stg_i = sb + 512 + (s) * STG_A;                                       \
        _Pragma("unroll")                                                              \
        for (int i = 0; i < 2; i++) {                                                  \
            int tok = toks[a_row[i]];                                                  \
            const __half* src = g_x16 + (size_t)(tok < 0 ? 0 : tok) * H_DIM + k0 + a_j[i] * 8; \
            cp16(stg_i + a_row[i] * 80 + a_j[i] * 16, src, tok >= 0 ? 16u : 0u);       \
        }                                                                              \
        cp16(stg_i + 10240 + b_row * 144 + b_j * 16,                                   \
             Wg + (size_t)(k0 + b_row) * F_DIM + b_j * 8, 16u);                        \
        cp16(stg_i + 14848 + b_row * 144 + b_j * 16,                                   \
             Wu + (size_t)(k0 + b_row) * F_DIM + b_j * 8, 16u);                        \
        cp_commit();                                                                   \
    }

    ISSUE_A(0, 0);
    ISSUE_A(1, 1);

    float accG[2][4][4], accU[2][4][4];
#pragma unroll
    for (int mt = 0; mt < 2; mt++)
#pragma unroll
        for (int nt = 0; nt < 4; nt++)
#pragma unroll
            for (int i = 0; i < 4; i++) { accG[mt][nt][i] = 0.f; accU[mt][nt][i] = 0.f; }

    uint32_t aOff = (uint32_t)((mb + (lane & 15)) * 80 + (lane >> 4) * 16);
    uint32_t bOff = (uint32_t)((lane & 15) * 144 + (lane >> 4) * 16);

    for (int c = 0; c < NCH; c++) {
        if (c + 1 < NCH) asm volatile("cp.async.wait_group 1;" ::: "memory");
        else             asm volatile("cp.async.wait_group 0;" ::: "memory");
        __syncthreads();
        if (c + 2 < NCH) ISSUE_A(c + 2, (c + 2) % 3);
        uint32_t stg = sb + 512 + (c % 3) * STG_A;
#pragma unroll
        for (int ks = 0; ks < 2; ks++) {
            uint32_t af[2][4];
#pragma unroll
            for (int mt = 0; mt < 2; mt++)
                ldsm4(af[mt], stg + aOff + mt * 16 * 80 + ks * 32);
            uint32_t bg[2][4], bu[2][4];
#pragma unroll
            for (int pr = 0; pr < 2; pr++) {
                uint32_t co = (uint32_t)((nb + pr * 16) * 2 + ks * 16 * 144);
                ldsm4t(bg[pr], stg + 10240 + bOff + co);
                ldsm4t(bu[pr], stg + 14848 + bOff + co);
            }
#pragma unroll
            for (int pr = 0; pr < 2; pr++)
#pragma unroll
                for (int hn = 0; hn < 2; hn++) {
                    int nt = pr * 2 + hn;
#pragma unroll
                    for (int mt = 0; mt < 2; mt++) {
                        mma_f16(accG[mt][nt], af[mt], bg[pr] + hn * 2);
                        mma_f16(accU[mt][nt], af[mt], bu[pr] + hn * 2);
                    }
                }
        }
    }

    // epilogue: silu(gate)*up -> g_h16
#pragma unroll
    for (int mt = 0; mt < 2; mt++)
#pragma unroll
        for (int half = 0; half < 2; half++) {
            int r = m0 + mb + mt * 16 + gid + half * 8;
            if (r < cnt) {
                __half* hp = g_h16 + (size_t)(base + r) * F_DIM + n0 + nb + tig * 2;
#pragma unroll
                for (int nt = 0; nt < 4; nt++) {
                    float h0 = silu_mul(accG[mt][nt][half * 2 + 0], accU[mt][nt][half * 2 + 0]);
                    float h1 = silu_mul(accG[mt][nt][half * 2 + 1], accU[mt][nt][half * 2 + 1]);
                    *(__half2*)(hp + nt * 8) = __floats2half2_rn(h0, h1);
                }
            }
        }
#undef ISSUE_A
}

// ================= pass B: out += w * (H1 Wd), fp16 mma, 256 threads, 2 CTA/SM =======
// CTA 128M x 128N, BK=32, 8 warps (4m x 2n), warp tile 32x64. M-block from flat table.
#define STG_B 18944
#define SMEM_B_BYTES (3 * STG_B)

__global__ void __launch_bounds__(256, 2)
gemmB_kernel(float* __restrict__ out) {
    int blk = blockIdx.y;
    if (blk >= g_nblk) return;
    int e = g_blk_e[blk];
    int m0 = g_blk_m[blk];
    int cnt = g_count[e];
    int base = g_off[e];
    int n0 = blockIdx.x * 128;

    extern __shared__ __align__(16) char dsm[];
    uint32_t sb = smem_u32(dsm);

    int tid = threadIdx.x, wid = tid >> 5, lane = tid & 31;
    int gid = lane >> 2, tig = lane & 3;
    int mb = (wid & 3) * 32;
    int nb = (wid >> 2) * 64;

    const __half* Wd = g_wd16 + (size_t)e * F_DIM * H_DIM + n0;

    int a_row[2], a_j[2], b_row[2], b_j[2];
#pragma unroll
    for (int i = 0; i < 2; i++) {
        int i2 = tid + i * 256;
        a_row[i] = i2 >> 2;  a_j[i] = i2 & 3;
        b_row[i] = i2 >> 4;  b_j[i] = i2 & 15;
    }

    const int NCH = F_DIM / 32;  // 128
#define ISSUE_B(c, s)                                                                  \
    {                                                                                  \
        int k0 = (c) * 32;                                                             \
        uint32_t stg_i = sb + (s) * STG_B;                                             \
        _Pragma("unroll")                                                              \
        for (int i = 0; i < 2; i++) {                                                  \
            int r = m0 + a_row[i];                                                     \
            int ok = (r < cnt);                                                        \
            const __half* src = g_h16 + (size_t)(base + (ok ? r : 0)) * F_DIM + k0 + a_j[i] * 8; \
            cp16(stg_i + a_row[i] * 80 + a_j[i] * 16, src, ok ? 16u : 0u);             \
            cp16(stg_i + 10240 + b_row[i] * 272 + b_j[i] * 16,                         \
                 Wd + (size_t)(k0 + b_row[i]) * H_DIM + b_j[i] * 8, 16u);              \
        }                                                                              \
        cp_commit();                                                                   \
    }

    ISSUE_B(0, 0);
    ISSUE_B(1, 1);

    float acc[2][8][4];
#pragma unroll
    for (int mt = 0; mt < 2; mt++)
#pragma unroll
        for (int nt = 0; nt < 8; nt++)
#pragma unroll
            for (int i = 0; i < 4; i++) acc[mt][nt][i] = 0.f;

    uint32_t aOff = (uint32_t)((mb + (lane & 15)) * 80 + (lane >> 4) * 16);
    uint32_t bOff = (uint32_t)((lane & 15) * 272 + (lane >> 4) * 16);

    for (int c = 0; c < NCH; c++) {
        if (c + 1 < NCH) asm volatile("cp.async.wait_group 1;" ::: "memory");
        else             asm volatile("cp.async.wait_group 0;" ::: "memory");
        __syncthreads();
        if (c + 2 < NCH) ISSUE_B(c + 2, (c + 2) % 3);
        uint32_t stg = sb + (c % 3) * STG_B;
#pragma unroll
        for (int ks = 0; ks < 2; ks++) {
            uint32_t af[2][4];
#pragma unroll
            for (int mt = 0; mt < 2; mt++)
                ldsm4(af[mt], stg + aOff + mt * 16 * 80 + ks * 32);
            uint32_t bf[4][4];
#pragma unroll
            for (int pr = 0; pr < 4; pr++) {
                uint32_t co = (uint32_t)((nb + pr * 16) * 2 + ks * 16 * 272);
                ldsm4t(bf[pr], stg + 10240 + bOff + co);
            }
#pragma unroll
            for (int pr = 0; pr < 4; pr++)
#pragma unroll
                for (int hn = 0; hn < 2; hn++) {
                    int nt = pr * 2 + hn;
#pragma unroll
                    for (int mt = 0; mt < 2; mt++)
                        mma_f16(acc[mt][nt], af[mt], bf[pr] + hn * 2);
                }
        }
    }

    // epilogue: weighted atomic combine
#pragma unroll
    for (int mt = 0; mt < 2; mt++)
#pragma unroll
        for (int half = 0; half < 2; half++) {
            int r = m0 + mb + mt * 16 + gid + half * 8;
            if (r < cnt) {
                int tok = g_slot_tok[base + r];
                float w = g_slot_w[base + r];
                float* op = out + (size_t)tok * H_DIM + n0 + nb + tig * 2;
#pragma unroll
                for (int nt = 0; nt < 8; nt++) {
                    atomicAdd(op + nt * 8 + 0, w * acc[mt][nt][half * 2 + 0]);
                    atomicAdd(op + nt * 8 + 1, w * acc[mt][nt][half * 2 + 1]);
                }
            }
        }
#undef ISSUE_B
}

// ---------------- launch: conv3 (main) ‖ init+router chain (side), join before GEMMs ----
extern "C" void kernel_launch(void* const* d_in, const int* in_sizes, int n_in,
                              void* d_out, int out_size) {
    const float* x  = (const float*)d_in[0];
    const float* gw = (const float*)d_in[1];
    const float* wg = (const float*)d_in[2];
    const float* wu = (const float*)d_in[3];
    const float* wd = (const float*)d_in[4];
    float* out = (float*)d_out;

    static cudaStream_t s1 = nullptr;
    static cudaEvent_t e0 = nullptr, e1 = nullptr;
    if (s1 == nullptr) {
        cudaStreamCreateWithFlags(&s1, cudaStreamNonBlocking);
        cudaEventCreateWithFlags(&e0, cudaEventDisableTiming);
        cudaEventCreateWithFlags(&e1, cudaEventDisableTiming);
        cudaFuncSetAttribute(gemmA_kernel, cudaFuncAttributeMaxDynamicSharedMemorySize, SMEM_A_BYTES);
        cudaFuncSetAttribute(gemmB_kernel, cudaFuncAttributeMaxDynamicSharedMemorySize, SMEM_B_BYTES);
    }

    __half* dg; __half* du; __half* dd;
    cudaGetSymbolAddress((void**)&dg, g_wg16);
    cudaGetSymbolAddress((void**)&du, g_wu16);
    cudaGetSymbolAddress((void**)&dd, g_wd16);
    const int NW = E_NUM * H_DIM * F_DIM;

    // fork
    cudaEventRecord(e0, 0);
    cudaStreamWaitEvent(s1, e0, 0);

    // side: init -> router -> scatter -> reduce (no GEMM running concurrently)
    init_kernel<<<512, 256, 0, s1>>>(out, out_size);
    router_kernel<<<T_TOK / 8, 256, 0, s1>>>(x, gw);   // also writes g_x16
    scatter_kernel<<<T_TOK / 256, 256, 0, s1>>>();     // publishes g_off + block table
    reduce_kernel<<<1, 256, 0, s1>>>(out, out_size);
    cudaEventRecord(e1, s1);

    // main: weight conversion
    dim3 gC(NW / 1024, 3);
    conv3_kernel<<<gC, 256>>>(wg, wu, wd, dg, du, dd, NW);

    // join, then GEMMs (flat M-block grids)
    cudaStreamWaitEvent(0, e1, 0);
    dim3 gA(F_DIM / 64, MAX_BLK);
    gemmA_kernel<<<gA, 256, SMEM_A_BYTES>>>();

    dim3 gB(H_DIM / 128, MAX_BLK);
    gemmB_kernel<<<gB, 256, SMEM_B_BYTES>>>(out);
}